// round 6
// baseline (speedup 1.0000x reference)
#include <cuda_runtime.h>
#include <cuda_bf16.h>
#include <math.h>
#include <stdint.h>

// Problem constants
#define B_ROWS 131072
#define FEAT 256
#define LATD 128
#define NIN 640           // 2*FEAT + LATD
#define HG 32
#define HID 512
#define NE 3

// ---------------------------------------------------------------------------
// Scratch (device globals — no runtime allocation allowed)
// ---------------------------------------------------------------------------
__device__ float g_u[(size_t)B_ROWS * HG];
__device__ float g_gate[(size_t)B_ROWS * NE];

__device__ __nv_bfloat16 g_xhi[(size_t)B_ROWS * NIN];
__device__ __nv_bfloat16 g_xlo[(size_t)B_ROWS * NIN];
__device__ __nv_bfloat16 g_h1hi[(size_t)B_ROWS * HID];
__device__ __nv_bfloat16 g_h1lo[(size_t)B_ROWS * HID];
__device__ __nv_bfloat16 g_h2hi[(size_t)B_ROWS * HID];
__device__ __nv_bfloat16 g_h2lo[(size_t)B_ROWS * HID];

__device__ __nv_bfloat16 g_w1hi[NE * HID * NIN];
__device__ __nv_bfloat16 g_w1lo[NE * HID * NIN];
__device__ __nv_bfloat16 g_w2hi[NE * HID * HID];
__device__ __nv_bfloat16 g_w2lo[NE * HID * HID];
__device__ __nv_bfloat16 g_w3hi[NE * HID * HID];
__device__ __nv_bfloat16 g_w3lo[NE * HID * HID];
__device__ __nv_bfloat16 g_w4hi[NE * LATD * HID];
__device__ __nv_bfloat16 g_w4lo[NE * LATD * HID];

// ---------------------------------------------------------------------------
// helpers
// ---------------------------------------------------------------------------
__device__ __forceinline__ uint32_t smem_u32(const void* p) {
    uint32_t a;
    asm("{ .reg .u64 t; cvta.to.shared.u64 t, %1; cvt.u32.u64 %0, t; }" : "=r"(a) : "l"(p));
    return a;
}

#define CP_ASYNC16(dst, src) \
    asm volatile("cp.async.cg.shared.global [%0], [%1], 16;" :: "r"(dst), "l"(src))
#define CP_COMMIT() asm volatile("cp.async.commit_group;" ::: "memory")
#define CP_WAIT0()  asm volatile("cp.async.wait_group 0;" ::: "memory")
#define CP_WAIT1()  asm volatile("cp.async.wait_group 1;" ::: "memory")

__device__ __forceinline__ void split_hilo(float v, __nv_bfloat16& h, __nv_bfloat16& l) {
    h = __float2bfloat16_rn(v);
    l = __float2bfloat16_rn(v - __bfloat162float(h));
}

__device__ __forceinline__ void mma16816(float* c, const unsigned* a, unsigned b0, unsigned b1) {
    asm volatile(
        "mma.sync.aligned.m16n8k16.row.col.f32.bf16.bf16.f32 "
        "{%0,%1,%2,%3}, {%4,%5,%6,%7}, {%8,%9}, {%0,%1,%2,%3};\n"
        : "+f"(c[0]), "+f"(c[1]), "+f"(c[2]), "+f"(c[3])
        : "r"(a[0]), "r"(a[1]), "r"(a[2]), "r"(a[3]), "r"(b0), "r"(b1));
}

__device__ __forceinline__ void ldmx4(unsigned* r, uint32_t addr) {
    asm volatile("ldmatrix.sync.aligned.m8n8.x4.shared.b16 {%0,%1,%2,%3}, [%4];"
                 : "=r"(r[0]), "=r"(r[1]), "=r"(r[2]), "=r"(r[3]) : "r"(addr));
}

// ---------------------------------------------------------------------------
// prep kernels (proven)
// ---------------------------------------------------------------------------
__global__ __launch_bounds__(256) void convert_hilo(
    const float* __restrict__ src, __nv_bfloat16* __restrict__ hi,
    __nv_bfloat16* __restrict__ lo, int n4)
{
    int i = blockIdx.x * blockDim.x + threadIdx.x;
    if (i >= n4) return;
    float4 v = reinterpret_cast<const float4*>(src)[i];
    __nv_bfloat16 h0, h1, h2, h3, l0, l1, l2, l3;
    split_hilo(v.x, h0, l0); split_hilo(v.y, h1, l1);
    split_hilo(v.z, h2, l2); split_hilo(v.w, h3, l3);
    __nv_bfloat162* hp = reinterpret_cast<__nv_bfloat162*>(hi) + i * 2;
    __nv_bfloat162* lp = reinterpret_cast<__nv_bfloat162*>(lo) + i * 2;
    hp[0] = __nv_bfloat162{h0, h1}; hp[1] = __nv_bfloat162{h2, h3};
    lp[0] = __nv_bfloat162{l0, l1}; lp[1] = __nv_bfloat162{l2, l3};
}

__global__ __launch_bounds__(256) void xprep_kernel(
    const float* __restrict__ f1, const float* __restrict__ f2,
    const float* __restrict__ lat)
{
    int i = blockIdx.x * blockDim.x + threadIdx.x;
    int row = i / (NIN / 4);
    int kk = (i % (NIN / 4)) * 4;
    float4 v;
    if (kk < FEAT)
        v = *reinterpret_cast<const float4*>(&f1[(size_t)row * FEAT + kk]);
    else if (kk < 2 * FEAT)
        v = *reinterpret_cast<const float4*>(&f2[(size_t)row * FEAT + kk - FEAT]);
    else
        v = *reinterpret_cast<const float4*>(&lat[(size_t)row * LATD + kk - 2 * FEAT]);
    __nv_bfloat16 h0, h1, h2, h3, l0, l1, l2, l3;
    split_hilo(v.x, h0, l0); split_hilo(v.y, h1, l1);
    split_hilo(v.z, h2, l2); split_hilo(v.w, h3, l3);
    size_t base = (size_t)row * NIN + kk;
    *reinterpret_cast<__nv_bfloat162*>(&g_xhi[base])     = __nv_bfloat162{h0, h1};
    *reinterpret_cast<__nv_bfloat162*>(&g_xhi[base + 2]) = __nv_bfloat162{h2, h3};
    *reinterpret_cast<__nv_bfloat162*>(&g_xlo[base])     = __nv_bfloat162{l0, l1};
    *reinterpret_cast<__nv_bfloat162*>(&g_xlo[base + 2]) = __nv_bfloat162{l2, l3};
}

__global__ __launch_bounds__(256) void gate0_kernel(
    const float* __restrict__ f1, const float* __restrict__ f2,
    const float* __restrict__ lat,
    const float* __restrict__ w, const float* __restrict__ bias)
{
    __shared__ float As[16][260];
    __shared__ float Ws[16][36];

    const int tid = threadIdx.x;
    const int tx = tid & 7;
    const int ty = tid >> 3;
    const int m0 = blockIdx.x * 256;

    float acc[8][4];
#pragma unroll
    for (int i = 0; i < 8; ++i)
#pragma unroll
        for (int j = 0; j < 4; ++j) acc[i][j] = 0.f;

    for (int k0 = 0; k0 < NIN; k0 += 16) {
#pragma unroll
        for (int r = 0; r < 4; ++r) {
            int idx = r * 256 + tid;
            int m = idx >> 2;
            int kq = (idx & 3) * 4;
            int kg = k0 + kq;
            float4 v;
            if (kg < FEAT)
                v = *reinterpret_cast<const float4*>(&f1[(size_t)(m0 + m) * FEAT + kg]);
            else if (kg < 2 * FEAT)
                v = *reinterpret_cast<const float4*>(&f2[(size_t)(m0 + m) * FEAT + (kg - FEAT)]);
            else
                v = *reinterpret_cast<const float4*>(&lat[(size_t)(m0 + m) * LATD + (kg - 2 * FEAT)]);
            As[kq + 0][m] = v.x; As[kq + 1][m] = v.y;
            As[kq + 2][m] = v.z; As[kq + 3][m] = v.w;
        }
        if (tid < 128) {
            int n = tid >> 2;
            int kq = (tid & 3) * 4;
            float4 v = *reinterpret_cast<const float4*>(&w[(size_t)n * NIN + k0 + kq]);
            Ws[kq + 0][n] = v.x; Ws[kq + 1][n] = v.y;
            Ws[kq + 2][n] = v.z; Ws[kq + 3][n] = v.w;
        }
        __syncthreads();
#pragma unroll
        for (int k = 0; k < 16; ++k) {
            const float4 a0 = *reinterpret_cast<const float4*>(&As[k][ty * 8]);
            const float4 a1 = *reinterpret_cast<const float4*>(&As[k][ty * 8 + 4]);
            const float4 b  = *reinterpret_cast<const float4*>(&Ws[k][tx * 4]);
            float av[8] = {a0.x, a0.y, a0.z, a0.w, a1.x, a1.y, a1.z, a1.w};
            float bv[4] = {b.x, b.y, b.z, b.w};
#pragma unroll
            for (int i = 0; i < 8; ++i)
#pragma unroll
                for (int j = 0; j < 4; ++j)
                    acc[i][j] = fmaf(av[i], bv[j], acc[i][j]);
        }
        __syncthreads();
    }

    float bb[4];
#pragma unroll
    for (int j = 0; j < 4; ++j) bb[j] = bias[tx * 4 + j];
#pragma unroll
    for (int i = 0; i < 8; ++i) {
        int m = m0 + ty * 8 + i;
        float4 o;
        o.x = acc[i][0] + bb[0];
        o.y = acc[i][1] + bb[1];
        o.z = acc[i][2] + bb[2];
        o.w = acc[i][3] + bb[3];
        *reinterpret_cast<float4*>(&g_u[(size_t)m * HG + tx * 4]) = o;
    }
}

__global__ __launch_bounds__(256) void gate1_kernel(
    const float* __restrict__ g1w, const float* __restrict__ g1b,
    const float* __restrict__ g2w, const float* __restrict__ g2b,
    float* __restrict__ out_gate)
{
    __shared__ float us[256][33];
    __shared__ float w1s[32][33];
    __shared__ float b1s[32];
    __shared__ float w2s[3][32];
    __shared__ float b2s[3];

    const int tid = threadIdx.x;
    const int m0 = blockIdx.x * 256;

    for (int idx = tid; idx < 256 * 32; idx += 256) {
        int r = idx >> 5, c = idx & 31;
        us[r][c] = g_u[(size_t)(m0 + r) * HG + c];
    }
    for (int idx = tid; idx < 32 * 32; idx += 256)
        w1s[idx >> 5][idx & 31] = g1w[idx];
    if (tid < 32) b1s[tid] = g1b[tid];
    if (tid < 96) w2s[tid / 32][tid % 32] = g2w[tid];
    if (tid < 3) b2s[tid] = g2b[tid];
    __syncthreads();

    const int m = m0 + tid;

    float eu[32];
#pragma unroll
    for (int k = 0; k < 32; ++k) {
        float x = us[tid][k];
        eu[k] = (x > 0.f) ? x : expm1f(x);
    }
    float ev[32];
#pragma unroll
    for (int j = 0; j < 32; ++j) {
        float v = b1s[j];
#pragma unroll
        for (int k = 0; k < 32; ++k) v = fmaf(eu[k], w1s[j][k], v);
        ev[j] = (v > 0.f) ? v : expm1f(v);
    }
    float s[3];
#pragma unroll
    for (int e = 0; e < 3; ++e) {
        float v = b2s[e];
#pragma unroll
        for (int j = 0; j < 32; ++j) v = fmaf(ev[j], w2s[e][j], v);
        s[e] = v;
    }
    float mx = fmaxf(s[0], fmaxf(s[1], s[2]));
    float p0 = expf(s[0] - mx);
    float p1 = expf(s[1] - mx);
    float p2 = expf(s[2] - mx);
    float inv = 1.f / (p0 + p1 + p2);
    p0 *= inv; p1 *= inv; p2 *= inv;

    g_gate[(size_t)m * 3 + 0] = p0;
    g_gate[(size_t)m * 3 + 1] = p1;
    g_gate[(size_t)m * 3 + 2] = p2;
    out_gate[(size_t)m * 3 + 0] = p0;
    out_gate[(size_t)m * 3 + 1] = p1;
    out_gate[(size_t)m * 3 + 2] = p2;
}

// ---------------------------------------------------------------------------
// blend_mma v3: cp.async 2-stage pipeline + ldmatrix fragment loads.
// Out[m,n] = act( sum_e gate[m,e] * ((A @ W_e^T)[m,n] + b_e[n]) )
// bf16 3-term compensated mma (hh + hl + lh), fp32 accumulate.
// Block tile: M=128 x N=64 x E=3, 8 warps (warp tile 32x32 per expert).
//
// smem per stage (bf16 units, row stride 72 = 64k + 8 pad):
//   A hi 128*72 | A lo 128*72 | W hi 192*72 | W lo 192*72   = 46080 units (92160B)
// ---------------------------------------------------------------------------
#define ASTRIDE 72
#define AROWS 128
#define WROWS 192
#define STAGE_U (2 * (AROWS + WROWS) * ASTRIDE)   // 46080 bf16 units

template <int KDIM, int NOUT>
__device__ __forceinline__ void prefetch_chunk(
    __nv_bfloat16* sm, int stage, int k0, int m0, int n0,
    const __nv_bfloat16* __restrict__ Ahi, const __nv_bfloat16* __restrict__ Alo,
    const __nv_bfloat16* __restrict__ Whi, const __nv_bfloat16* __restrict__ Wlo)
{
    const int tid = threadIdx.x;
    const uint32_t base = smem_u32(sm) + (uint32_t)stage * STAGE_U * 2;
#pragma unroll
    for (int it = 0; it < 20; ++it) {
        int i = tid + it * 256;               // 0..5119
        uint32_t dst;
        const __nv_bfloat16* src;
        if (i < 2048) {
            int plane = i >> 10;              // 0 hi, 1 lo
            int idx = i & 1023;
            int row = idx >> 3, c = idx & 7;
            const __nv_bfloat16* Ap = plane ? Alo : Ahi;
            src = Ap + (size_t)(m0 + row) * KDIM + k0 + c * 8;
            dst = base + (uint32_t)(plane * AROWS * ASTRIDE + row * ASTRIDE + c * 8) * 2;
        } else {
            int j = i - 2048;                 // 0..3071
            int plane = j / 1536;
            int idx = j - plane * 1536;
            int r = idx >> 3, c = idx & 7;    // r in [0,192)
            int e = r >> 6, n = r & 63;
            const __nv_bfloat16* Wp = plane ? Wlo : Whi;
            src = Wp + ((size_t)e * NOUT + n0 + n) * KDIM + k0 + c * 8;
            dst = base + (uint32_t)(2 * AROWS * ASTRIDE + plane * WROWS * ASTRIDE +
                                    r * ASTRIDE + c * 8) * 2;
        }
        CP_ASYNC16(dst, src);
    }
}

template <int KDIM, int NOUT, bool RELU, bool FP32OUT>
__global__ __launch_bounds__(256, 1) void blend_mma(
    const __nv_bfloat16* __restrict__ Ahi, const __nv_bfloat16* __restrict__ Alo,
    const __nv_bfloat16* __restrict__ Whi, const __nv_bfloat16* __restrict__ Wlo,
    const float* __restrict__ bias,
    __nv_bfloat16* __restrict__ Ohi, __nv_bfloat16* __restrict__ Olo,
    float* __restrict__ Ofp)
{
    extern __shared__ __nv_bfloat16 smbuf[];

    const int tid = threadIdx.x;
    const int m0 = blockIdx.y * 128;
    const int n0 = blockIdx.x * 64;
    const int w = tid >> 5, lane = tid & 31;
    const int wm = w & 3, wn = w >> 2;          // warps: 4 along M, 2 along N
    const int g = lane >> 2, t = lane & 3;

    // ldmatrix per-lane addressing: tile index and row-in-tile
    const int lt = lane >> 3, lr = lane & 7;
    const int a_ro = (lt & 1) * 8 + lr;         // row offset within 16-row frag
    const int a_ko = (lt >> 1) * 8;             // k offset (0 or 8)

    const uint32_t smU = smem_u32(smbuf);
    // A fragment base addresses (bytes), per mt, hi/lo plane
    uint32_t aAddr[2][2];
#pragma unroll
    for (int mt = 0; mt < 2; ++mt) {
#pragma unroll
        for (int pl = 0; pl < 2; ++pl)
            aAddr[mt][pl] = smU + (uint32_t)((pl * AROWS + wm * 32 + mt * 16 + a_ro) * ASTRIDE + a_ko) * 2;
    }
    // W fragment base addresses, per expert, per n16-half, hi/lo
    uint32_t wAddr[3][2][2];
#pragma unroll
    for (int e = 0; e < 3; ++e)
#pragma unroll
        for (int hf = 0; hf < 2; ++hf)
#pragma unroll
            for (int pl = 0; pl < 2; ++pl)
                wAddr[e][hf][pl] = smU + (uint32_t)(2 * AROWS * ASTRIDE + pl * WROWS * ASTRIDE +
                    (e * 64 + wn * 32 + hf * 16 + a_ro) * ASTRIDE + a_ko) * 2;

    // preload gate + bias into registers (hide global latency under mainloop)
    float gv[2][2][3];   // [mt][h][expert]
#pragma unroll
    for (int mt = 0; mt < 2; ++mt)
#pragma unroll
        for (int h = 0; h < 2; ++h) {
            int m = m0 + wm * 32 + mt * 16 + g + h * 8;
            gv[mt][h][0] = g_gate[(size_t)m * 3 + 0];
            gv[mt][h][1] = g_gate[(size_t)m * 3 + 1];
            gv[mt][h][2] = g_gate[(size_t)m * 3 + 2];
        }
    float bb[3][4][2];
#pragma unroll
    for (int e = 0; e < 3; ++e)
#pragma unroll
        for (int nt = 0; nt < 4; ++nt) {
            int n = n0 + wn * 32 + nt * 8 + t * 2;
            bb[e][nt][0] = bias[e * NOUT + n];
            bb[e][nt][1] = bias[e * NOUT + n + 1];
        }

    float acc[3][2][4][4];
#pragma unroll
    for (int e = 0; e < 3; ++e)
#pragma unroll
        for (int mt = 0; mt < 2; ++mt)
#pragma unroll
            for (int nt = 0; nt < 4; ++nt)
#pragma unroll
                for (int c = 0; c < 4; ++c) acc[e][mt][nt][c] = 0.f;

    constexpr int NCH = KDIM / 64;

    prefetch_chunk<KDIM, NOUT>(smbuf, 0, 0, m0, n0, Ahi, Alo, Whi, Wlo);
    CP_COMMIT();

    for (int ch = 0; ch < NCH; ++ch) {
        const int cur = ch & 1;
        if (ch + 1 < NCH) {
            prefetch_chunk<KDIM, NOUT>(smbuf, cur ^ 1, (ch + 1) * 64, m0, n0,
                                       Ahi, Alo, Whi, Wlo);
            CP_COMMIT();
            CP_WAIT1();
        } else {
            CP_WAIT0();
        }
        __syncthreads();

        const uint32_t stOff = (uint32_t)cur * STAGE_U * 2;

#pragma unroll
        for (int ks = 0; ks < 64; ks += 16) {
            const uint32_t ko = stOff + ks * 2;
            unsigned ah[2][4], al[2][4];
            ldmx4(ah[0], aAddr[0][0] + ko);
            ldmx4(ah[1], aAddr[1][0] + ko);
            ldmx4(al[0], aAddr[0][1] + ko);
            ldmx4(al[1], aAddr[1][1] + ko);
#pragma unroll
            for (int e = 0; e < 3; ++e) {
                unsigned bh0[4], bh1[4], bl0[4], bl1[4];
                ldmx4(bh0, wAddr[e][0][0] + ko);
                ldmx4(bh1, wAddr[e][1][0] + ko);
                ldmx4(bl0, wAddr[e][0][1] + ko);
                ldmx4(bl1, wAddr[e][1][1] + ko);
#pragma unroll
                for (int mt = 0; mt < 2; ++mt) {
                    // nt0 = {bh0[0],bh0[2]}, nt1 = {bh0[1],bh0[3]},
                    // nt2 = {bh1[0],bh1[2]}, nt3 = {bh1[1],bh1[3]}
                    mma16816(acc[e][mt][0], ah[mt], bh0[0], bh0[2]);
                    mma16816(acc[e][mt][1], ah[mt], bh0[1], bh0[3]);
                    mma16816(acc[e][mt][2], ah[mt], bh1[0], bh1[2]);
                    mma16816(acc[e][mt][3], ah[mt], bh1[1], bh1[3]);
                    mma16816(acc[e][mt][0], ah[mt], bl0[0], bl0[2]);
                    mma16816(acc[e][mt][1], ah[mt], bl0[1], bl0[3]);
                    mma16816(acc[e][mt][2], ah[mt], bl1[0], bl1[2]);
                    mma16816(acc[e][mt][3], ah[mt], bl1[1], bl1[3]);
                    mma16816(acc[e][mt][0], al[mt], bh0[0], bh0[2]);
                    mma16816(acc[e][mt][1], al[mt], bh0[1], bh0[3]);
                    mma16816(acc[e][mt][2], al[mt], bh1[0], bh1[2]);
                    mma16816(acc[e][mt][3], al[mt], bh1[1], bh1[3]);
                }
            }
        }
        __syncthreads();
    }

    // ---------------- epilogue (all operands in registers) ----------------
#pragma unroll
    for (int mt = 0; mt < 2; ++mt)
#pragma unroll
        for (int h = 0; h < 2; ++h) {
            int m = m0 + wm * 32 + mt * 16 + g + h * 8;
            float ga = gv[mt][h][0], gb = gv[mt][h][1], gc = gv[mt][h][2];
#pragma unroll
            for (int nt = 0; nt < 4; ++nt) {
                int n = n0 + wn * 32 + nt * 8 + t * 2;
                float v0 = ga * (acc[0][mt][nt][h * 2 + 0] + bb[0][nt][0])
                         + gb * (acc[1][mt][nt][h * 2 + 0] + bb[1][nt][0])
                         + gc * (acc[2][mt][nt][h * 2 + 0] + bb[2][nt][0]);
                float v1 = ga * (acc[0][mt][nt][h * 2 + 1] + bb[0][nt][1])
                         + gb * (acc[1][mt][nt][h * 2 + 1] + bb[1][nt][1])
                         + gc * (acc[2][mt][nt][h * 2 + 1] + bb[2][nt][1]);
                if (RELU) { v0 = fmaxf(v0, 0.f); v1 = fmaxf(v1, 0.f); }
                if (FP32OUT) {
                    float2 o = {v0, v1};
                    *reinterpret_cast<float2*>(&Ofp[(size_t)m * NOUT + n]) = o;
                } else {
                    __nv_bfloat16 h0, h1, l0, l1;
                    split_hilo(v0, h0, l0);
                    split_hilo(v1, h1, l1);
                    *reinterpret_cast<__nv_bfloat162*>(&Ohi[(size_t)m * NOUT + n]) = __nv_bfloat162{h0, h1};
                    *reinterpret_cast<__nv_bfloat162*>(&Olo[(size_t)m * NOUT + n]) = __nv_bfloat162{l0, l1};
                }
            }
        }
}

// ---------------------------------------------------------------------------
// Launch
// ---------------------------------------------------------------------------
extern "C" void kernel_launch(void* const* d_in, const int* in_sizes, int n_in,
                              void* d_out, int out_size)
{
    const float* f1  = (const float*)d_in[0];
    const float* f2  = (const float*)d_in[1];
    const float* lat = (const float*)d_in[2];
    const float* g0w = (const float*)d_in[3];
    const float* g0b = (const float*)d_in[4];
    const float* g1w = (const float*)d_in[5];
    const float* g1b = (const float*)d_in[6];
    const float* g2w = (const float*)d_in[7];
    const float* g2b = (const float*)d_in[8];
    const float* W1  = (const float*)d_in[9];
    const float* b1  = (const float*)d_in[10];
    const float* W2  = (const float*)d_in[11];
    const float* b2  = (const float*)d_in[12];
    const float* W3  = (const float*)d_in[13];
    const float* b3  = (const float*)d_in[14];
    const float* W4  = (const float*)d_in[15];
    const float* b4  = (const float*)d_in[16];

    float* out      = (float*)d_out;
    float* gate_out = out + (size_t)B_ROWS * LATD;

    __nv_bfloat16 *w1hi, *w1lo, *w2hi, *w2lo, *w3hi, *w3lo, *w4hi, *w4lo;
    __nv_bfloat16 *xhi, *xlo, *h1hi, *h1lo, *h2hi, *h2lo;
    cudaGetSymbolAddress((void**)&w1hi, g_w1hi); cudaGetSymbolAddress((void**)&w1lo, g_w1lo);
    cudaGetSymbolAddress((void**)&w2hi, g_w2hi); cudaGetSymbolAddress((void**)&w2lo, g_w2lo);
    cudaGetSymbolAddress((void**)&w3hi, g_w3hi); cudaGetSymbolAddress((void**)&w3lo, g_w3lo);
    cudaGetSymbolAddress((void**)&w4hi, g_w4hi); cudaGetSymbolAddress((void**)&w4lo, g_w4lo);
    cudaGetSymbolAddress((void**)&xhi,  g_xhi);  cudaGetSymbolAddress((void**)&xlo,  g_xlo);
    cudaGetSymbolAddress((void**)&h1hi, g_h1hi); cudaGetSymbolAddress((void**)&h1lo, g_h1lo);
    cudaGetSymbolAddress((void**)&h2hi, g_h2hi); cudaGetSymbolAddress((void**)&h2lo, g_h2lo);

    // conversions
    {
        int n4 = NE * HID * NIN / 4;
        convert_hilo<<<(n4 + 255) / 256, 256>>>(W1, w1hi, w1lo, n4);
        n4 = NE * HID * HID / 4;
        convert_hilo<<<(n4 + 255) / 256, 256>>>(W2, w2hi, w2lo, n4);
        convert_hilo<<<(n4 + 255) / 256, 256>>>(W3, w3hi, w3lo, n4);
        n4 = NE * LATD * HID / 4;
        convert_hilo<<<(n4 + 255) / 256, 256>>>(W4, w4hi, w4lo, n4);
        int nx = B_ROWS * (NIN / 4);
        xprep_kernel<<<nx / 256, 256>>>(f1, f2, lat);
    }

    // gate path
    gate0_kernel<<<B_ROWS / 256, 256>>>(f1, f2, lat, g0w, g0b);
    gate1_kernel<<<B_ROWS / 256, 256>>>(g1w, g1b, g2w, g2b, gate_out);

    // blend layers — dynamic smem (2 stages of 92160B)
    constexpr int SMEM_BYTES = 2 * STAGE_U * 2;   // 184320

    cudaFuncSetAttribute(blend_mma<NIN, HID, true, false>,
                         cudaFuncAttributeMaxDynamicSharedMemorySize, SMEM_BYTES);
    cudaFuncSetAttribute(blend_mma<HID, HID, true, false>,
                         cudaFuncAttributeMaxDynamicSharedMemorySize, SMEM_BYTES);
    cudaFuncSetAttribute(blend_mma<HID, LATD, false, true>,
                         cudaFuncAttributeMaxDynamicSharedMemorySize, SMEM_BYTES);

    dim3 grid1(HID / 64, B_ROWS / 128);
    blend_mma<NIN, HID, true, false><<<grid1, 256, SMEM_BYTES>>>(
        xhi, xlo, w1hi, w1lo, b1, h1hi, h1lo, nullptr);
    blend_mma<HID, HID, true, false><<<grid1, 256, SMEM_BYTES>>>(
        h1hi, h1lo, w2hi, w2lo, b2, h2hi, h2lo, nullptr);
    blend_mma<HID, HID, true, false><<<grid1, 256, SMEM_BYTES>>>(
        h2hi, h2lo, w3hi, w3lo, b3, h1hi, h1lo, nullptr);

    dim3 grid4(LATD / 64, B_ROWS / 128);
    blend_mma<HID, LATD, false, true><<<grid4, 256, SMEM_BYTES>>>(
        h1hi, h1lo, w4hi, w4lo, b4, nullptr, nullptr, out);
}

// round 7
// speedup vs baseline: 1.1209x; 1.1209x over previous
#include <cuda_runtime.h>
#include <cuda_bf16.h>
#include <math.h>
#include <stdint.h>

// Problem constants
#define B_ROWS 131072
#define FEAT 256
#define LATD 128
#define NIN 640           // 2*FEAT + LATD
#define HG 32
#define HID 512
#define NE 3

// ---------------------------------------------------------------------------
// Scratch (device globals — no runtime allocation allowed)
// ---------------------------------------------------------------------------
__device__ float g_u[(size_t)B_ROWS * HG];
__device__ float g_gate[(size_t)B_ROWS * NE];

__device__ __nv_bfloat16 g_xhi[(size_t)B_ROWS * NIN];
__device__ __nv_bfloat16 g_xlo[(size_t)B_ROWS * NIN];
__device__ __nv_bfloat16 g_h1hi[(size_t)B_ROWS * HID];
__device__ __nv_bfloat16 g_h1lo[(size_t)B_ROWS * HID];
__device__ __nv_bfloat16 g_h2hi[(size_t)B_ROWS * HID];
__device__ __nv_bfloat16 g_h2lo[(size_t)B_ROWS * HID];

__device__ __nv_bfloat16 g_w1hi[NE * HID * NIN];
__device__ __nv_bfloat16 g_w1lo[NE * HID * NIN];
__device__ __nv_bfloat16 g_w2hi[NE * HID * HID];
__device__ __nv_bfloat16 g_w2lo[NE * HID * HID];
__device__ __nv_bfloat16 g_w3hi[NE * HID * HID];
__device__ __nv_bfloat16 g_w3lo[NE * HID * HID];
__device__ __nv_bfloat16 g_w4hi[NE * LATD * HID];
__device__ __nv_bfloat16 g_w4lo[NE * LATD * HID];

// ---------------------------------------------------------------------------
// helpers
// ---------------------------------------------------------------------------
__device__ __forceinline__ uint32_t smem_u32(const void* p) {
    uint32_t a;
    asm("{ .reg .u64 t; cvta.to.shared.u64 t, %1; cvt.u32.u64 %0, t; }" : "=r"(a) : "l"(p));
    return a;
}

#define CP_ASYNC16(dst, src) \
    asm volatile("cp.async.cg.shared.global [%0], [%1], 16;" :: "r"(dst), "l"(src))
#define CP_COMMIT() asm volatile("cp.async.commit_group;" ::: "memory")
#define CP_WAIT0()  asm volatile("cp.async.wait_group 0;" ::: "memory")
#define CP_WAIT1()  asm volatile("cp.async.wait_group 1;" ::: "memory")

__device__ __forceinline__ void split_hilo(float v, __nv_bfloat16& h, __nv_bfloat16& l) {
    h = __float2bfloat16_rn(v);
    l = __float2bfloat16_rn(v - __bfloat162float(h));
}

__device__ __forceinline__ void mma16816(float* c, const unsigned* a, const unsigned* b) {
    asm volatile(
        "mma.sync.aligned.m16n8k16.row.col.f32.bf16.bf16.f32 "
        "{%0,%1,%2,%3}, {%4,%5,%6,%7}, {%8,%9}, {%0,%1,%2,%3};\n"
        : "+f"(c[0]), "+f"(c[1]), "+f"(c[2]), "+f"(c[3])
        : "r"(a[0]), "r"(a[1]), "r"(a[2]), "r"(a[3]), "r"(b[0]), "r"(b[1]));
}

__device__ __forceinline__ unsigned lds32(const __nv_bfloat16* p) {
    return *reinterpret_cast<const unsigned*>(p);
}

// ---------------------------------------------------------------------------
// prep kernels (proven)
// ---------------------------------------------------------------------------
__global__ __launch_bounds__(256) void convert_hilo(
    const float* __restrict__ src, __nv_bfloat16* __restrict__ hi,
    __nv_bfloat16* __restrict__ lo, int n4)
{
    int i = blockIdx.x * blockDim.x + threadIdx.x;
    if (i >= n4) return;
    float4 v = reinterpret_cast<const float4*>(src)[i];
    __nv_bfloat16 h0, h1, h2, h3, l0, l1, l2, l3;
    split_hilo(v.x, h0, l0); split_hilo(v.y, h1, l1);
    split_hilo(v.z, h2, l2); split_hilo(v.w, h3, l3);
    __nv_bfloat162* hp = reinterpret_cast<__nv_bfloat162*>(hi) + i * 2;
    __nv_bfloat162* lp = reinterpret_cast<__nv_bfloat162*>(lo) + i * 2;
    hp[0] = __nv_bfloat162{h0, h1}; hp[1] = __nv_bfloat162{h2, h3};
    lp[0] = __nv_bfloat162{l0, l1}; lp[1] = __nv_bfloat162{l2, l3};
}

__global__ __launch_bounds__(256) void xprep_kernel(
    const float* __restrict__ f1, const float* __restrict__ f2,
    const float* __restrict__ lat)
{
    int i = blockIdx.x * blockDim.x + threadIdx.x;
    int row = i / (NIN / 4);
    int kk = (i % (NIN / 4)) * 4;
    float4 v;
    if (kk < FEAT)
        v = *reinterpret_cast<const float4*>(&f1[(size_t)row * FEAT + kk]);
    else if (kk < 2 * FEAT)
        v = *reinterpret_cast<const float4*>(&f2[(size_t)row * FEAT + kk - FEAT]);
    else
        v = *reinterpret_cast<const float4*>(&lat[(size_t)row * LATD + kk - 2 * FEAT]);
    __nv_bfloat16 h0, h1, h2, h3, l0, l1, l2, l3;
    split_hilo(v.x, h0, l0); split_hilo(v.y, h1, l1);
    split_hilo(v.z, h2, l2); split_hilo(v.w, h3, l3);
    size_t base = (size_t)row * NIN + kk;
    *reinterpret_cast<__nv_bfloat162*>(&g_xhi[base])     = __nv_bfloat162{h0, h1};
    *reinterpret_cast<__nv_bfloat162*>(&g_xhi[base + 2]) = __nv_bfloat162{h2, h3};
    *reinterpret_cast<__nv_bfloat162*>(&g_xlo[base])     = __nv_bfloat162{l0, l1};
    *reinterpret_cast<__nv_bfloat162*>(&g_xlo[base + 2]) = __nv_bfloat162{l2, l3};
}

__global__ __launch_bounds__(256) void gate0_kernel(
    const float* __restrict__ f1, const float* __restrict__ f2,
    const float* __restrict__ lat,
    const float* __restrict__ w, const float* __restrict__ bias)
{
    __shared__ float As[16][260];
    __shared__ float Ws[16][36];

    const int tid = threadIdx.x;
    const int tx = tid & 7;
    const int ty = tid >> 3;
    const int m0 = blockIdx.x * 256;

    float acc[8][4];
#pragma unroll
    for (int i = 0; i < 8; ++i)
#pragma unroll
        for (int j = 0; j < 4; ++j) acc[i][j] = 0.f;

    for (int k0 = 0; k0 < NIN; k0 += 16) {
#pragma unroll
        for (int r = 0; r < 4; ++r) {
            int idx = r * 256 + tid;
            int m = idx >> 2;
            int kq = (idx & 3) * 4;
            int kg = k0 + kq;
            float4 v;
            if (kg < FEAT)
                v = *reinterpret_cast<const float4*>(&f1[(size_t)(m0 + m) * FEAT + kg]);
            else if (kg < 2 * FEAT)
                v = *reinterpret_cast<const float4*>(&f2[(size_t)(m0 + m) * FEAT + (kg - FEAT)]);
            else
                v = *reinterpret_cast<const float4*>(&lat[(size_t)(m0 + m) * LATD + (kg - 2 * FEAT)]);
            As[kq + 0][m] = v.x; As[kq + 1][m] = v.y;
            As[kq + 2][m] = v.z; As[kq + 3][m] = v.w;
        }
        if (tid < 128) {
            int n = tid >> 2;
            int kq = (tid & 3) * 4;
            float4 v = *reinterpret_cast<const float4*>(&w[(size_t)n * NIN + k0 + kq]);
            Ws[kq + 0][n] = v.x; Ws[kq + 1][n] = v.y;
            Ws[kq + 2][n] = v.z; Ws[kq + 3][n] = v.w;
        }
        __syncthreads();
#pragma unroll
        for (int k = 0; k < 16; ++k) {
            const float4 a0 = *reinterpret_cast<const float4*>(&As[k][ty * 8]);
            const float4 a1 = *reinterpret_cast<const float4*>(&As[k][ty * 8 + 4]);
            const float4 b  = *reinterpret_cast<const float4*>(&Ws[k][tx * 4]);
            float av[8] = {a0.x, a0.y, a0.z, a0.w, a1.x, a1.y, a1.z, a1.w};
            float bv[4] = {b.x, b.y, b.z, b.w};
#pragma unroll
            for (int i = 0; i < 8; ++i)
#pragma unroll
                for (int j = 0; j < 4; ++j)
                    acc[i][j] = fmaf(av[i], bv[j], acc[i][j]);
        }
        __syncthreads();
    }

    float bb[4];
#pragma unroll
    for (int j = 0; j < 4; ++j) bb[j] = bias[tx * 4 + j];
#pragma unroll
    for (int i = 0; i < 8; ++i) {
        int m = m0 + ty * 8 + i;
        float4 o;
        o.x = acc[i][0] + bb[0];
        o.y = acc[i][1] + bb[1];
        o.z = acc[i][2] + bb[2];
        o.w = acc[i][3] + bb[3];
        *reinterpret_cast<float4*>(&g_u[(size_t)m * HG + tx * 4]) = o;
    }
}

__global__ __launch_bounds__(256) void gate1_kernel(
    const float* __restrict__ g1w, const float* __restrict__ g1b,
    const float* __restrict__ g2w, const float* __restrict__ g2b,
    float* __restrict__ out_gate)
{
    __shared__ float us[256][33];
    __shared__ float w1s[32][33];
    __shared__ float b1s[32];
    __shared__ float w2s[3][32];
    __shared__ float b2s[3];

    const int tid = threadIdx.x;
    const int m0 = blockIdx.x * 256;

    for (int idx = tid; idx < 256 * 32; idx += 256) {
        int r = idx >> 5, c = idx & 31;
        us[r][c] = g_u[(size_t)(m0 + r) * HG + c];
    }
    for (int idx = tid; idx < 32 * 32; idx += 256)
        w1s[idx >> 5][idx & 31] = g1w[idx];
    if (tid < 32) b1s[tid] = g1b[tid];
    if (tid < 96) w2s[tid / 32][tid % 32] = g2w[tid];
    if (tid < 3) b2s[tid] = g2b[tid];
    __syncthreads();

    const int m = m0 + tid;

    float eu[32];
#pragma unroll
    for (int k = 0; k < 32; ++k) {
        float x = us[tid][k];
        eu[k] = (x > 0.f) ? x : expm1f(x);
    }
    float ev[32];
#pragma unroll
    for (int j = 0; j < 32; ++j) {
        float v = b1s[j];
#pragma unroll
        for (int k = 0; k < 32; ++k) v = fmaf(eu[k], w1s[j][k], v);
        ev[j] = (v > 0.f) ? v : expm1f(v);
    }
    float s[3];
#pragma unroll
    for (int e = 0; e < 3; ++e) {
        float v = b2s[e];
#pragma unroll
        for (int j = 0; j < 32; ++j) v = fmaf(ev[j], w2s[e][j], v);
        s[e] = v;
    }
    float mx = fmaxf(s[0], fmaxf(s[1], s[2]));
    float p0 = expf(s[0] - mx);
    float p1 = expf(s[1] - mx);
    float p2 = expf(s[2] - mx);
    float inv = 1.f / (p0 + p1 + p2);
    p0 *= inv; p1 *= inv; p2 *= inv;

    g_gate[(size_t)m * 3 + 0] = p0;
    g_gate[(size_t)m * 3 + 1] = p1;
    g_gate[(size_t)m * 3 + 2] = p2;
    out_gate[(size_t)m * 3 + 0] = p0;
    out_gate[(size_t)m * 3 + 1] = p1;
    out_gate[(size_t)m * 3 + 2] = p2;
}

// ---------------------------------------------------------------------------
// blend_mma v4: PERSISTENT CTAs + cp.async 2-stage pipeline across tiles.
// Out[m,n] = act( sum_e gate[m,e] * ((A @ W_e^T)[m,n] + b_e[n]) )
// bf16 3-term compensated mma (hh + hl + lh), fp32 accumulate.
// Block tile: M=128 x N=64 x E=3, 8 warps (warp tile 32x32 per expert).
// Tile order: n-fastest (A m-slab reused NOUT/64 times via L2).
//
// smem per stage (bf16 units, row stride 72 = 64k + 8 pad):
//   A hi 128*72 | A lo 128*72 | W hi 192*72 | W lo 192*72   = 46080 units (92160B)
// ---------------------------------------------------------------------------
#define ASTRIDE 72
#define AROWS 128
#define WROWS 192
#define STAGE_U (2 * (AROWS + WROWS) * ASTRIDE)   // 46080 bf16 units

template <int KDIM, int NOUT>
__device__ __forceinline__ void prefetch_chunk(
    __nv_bfloat16* sm, int stage, int k0, int m0, int n0,
    const __nv_bfloat16* __restrict__ Ahi, const __nv_bfloat16* __restrict__ Alo,
    const __nv_bfloat16* __restrict__ Whi, const __nv_bfloat16* __restrict__ Wlo)
{
    const int tid = threadIdx.x;
    const uint32_t base = smem_u32(sm) + (uint32_t)stage * STAGE_U * 2;
#pragma unroll
    for (int it = 0; it < 20; ++it) {
        int i = tid + it * 256;               // 0..5119
        uint32_t dst;
        const __nv_bfloat16* src;
        if (i < 2048) {
            int plane = i >> 10;              // 0 hi, 1 lo
            int idx = i & 1023;
            int row = idx >> 3, c = idx & 7;
            const __nv_bfloat16* Ap = plane ? Alo : Ahi;
            src = Ap + (size_t)(m0 + row) * KDIM + k0 + c * 8;
            dst = base + (uint32_t)(plane * AROWS * ASTRIDE + row * ASTRIDE + c * 8) * 2;
        } else {
            int j = i - 2048;                 // 0..3071
            int plane = j / 1536;
            int idx = j - plane * 1536;
            int r = idx >> 3, c = idx & 7;    // r in [0,192)
            int e = r >> 6, n = r & 63;
            const __nv_bfloat16* Wp = plane ? Wlo : Whi;
            src = Wp + ((size_t)e * NOUT + n0 + n) * KDIM + k0 + c * 8;
            dst = base + (uint32_t)(2 * AROWS * ASTRIDE + plane * WROWS * ASTRIDE +
                                    r * ASTRIDE + c * 8) * 2;
        }
        CP_ASYNC16(dst, src);
    }
}

template <int KDIM, int NOUT, bool RELU, bool FP32OUT>
__global__ __launch_bounds__(256, 1) void blend_mma(
    const __nv_bfloat16* __restrict__ Ahi, const __nv_bfloat16* __restrict__ Alo,
    const __nv_bfloat16* __restrict__ Whi, const __nv_bfloat16* __restrict__ Wlo,
    const float* __restrict__ bias,
    __nv_bfloat16* __restrict__ Ohi, __nv_bfloat16* __restrict__ Olo,
    float* __restrict__ Ofp)
{
    extern __shared__ __nv_bfloat16 smbuf[];

    constexpr int NTN = NOUT / 64;            // n-tiles (power of 2)
    constexpr int NT = (B_ROWS / 128) * NTN;  // total tiles
    constexpr int NCH = KDIM / 64;

    const int tid = threadIdx.x;
    const int w = tid >> 5, lane = tid & 31;
    const int wm = w & 3, wn = w >> 2;        // warps: 4 along M, 2 along N
    const int g = lane >> 2, t = lane & 3;
    const int stride = gridDim.x;

    int tile = blockIdx.x;
    if (tile >= NT) return;

    // prologue: prefetch chunk 0 of first tile into buf 0
    {
        int m0 = (tile / NTN) * 128, n0 = (tile % NTN) * 64;
        prefetch_chunk<KDIM, NOUT>(smbuf, 0, 0, m0, n0, Ahi, Alo, Whi, Wlo);
        CP_COMMIT();
    }
    int buf = 0;

    while (tile < NT) {
        const int m0 = (tile / NTN) * 128;
        const int n0 = (tile % NTN) * 64;

        // per-tile preload: gate + bias into registers (latency hidden by pipeline)
        float gv[2][2][3];
#pragma unroll
        for (int mt = 0; mt < 2; ++mt)
#pragma unroll
            for (int h = 0; h < 2; ++h) {
                int m = m0 + wm * 32 + mt * 16 + g + h * 8;
                gv[mt][h][0] = g_gate[(size_t)m * 3 + 0];
                gv[mt][h][1] = g_gate[(size_t)m * 3 + 1];
                gv[mt][h][2] = g_gate[(size_t)m * 3 + 2];
            }
        float bb[3][4][2];
#pragma unroll
        for (int e = 0; e < 3; ++e)
#pragma unroll
            for (int nt = 0; nt < 4; ++nt) {
                int n = n0 + wn * 32 + nt * 8 + t * 2;
                bb[e][nt][0] = bias[e * NOUT + n];
                bb[e][nt][1] = bias[e * NOUT + n + 1];
            }

        float acc[3][2][4][4];
#pragma unroll
        for (int e = 0; e < 3; ++e)
#pragma unroll
            for (int mt = 0; mt < 2; ++mt)
#pragma unroll
                for (int nt = 0; nt < 4; ++nt)
#pragma unroll
                    for (int c = 0; c < 4; ++c) acc[e][mt][nt][c] = 0.f;

        for (int ch = 0; ch < NCH; ++ch) {
            // prefetch next chunk (possibly of next tile) into other buffer
            int ntile, nch;
            if (ch + 1 < NCH) { ntile = tile; nch = ch + 1; }
            else { ntile = tile + stride; nch = 0; }
            if (ntile < NT) {
                int nm0 = (ntile / NTN) * 128, nn0 = (ntile % NTN) * 64;
                prefetch_chunk<KDIM, NOUT>(smbuf, buf ^ 1, nch * 64, nm0, nn0,
                                           Ahi, Alo, Whi, Wlo);
                CP_COMMIT();
                CP_WAIT1();
            } else {
                CP_WAIT0();
            }
            __syncthreads();

            const __nv_bfloat16* sAh = smbuf + buf * STAGE_U;
            const __nv_bfloat16* sAl = sAh + AROWS * ASTRIDE;
            const __nv_bfloat16* sWh = sAl + AROWS * ASTRIDE;
            const __nv_bfloat16* sWl = sWh + WROWS * ASTRIDE;

#pragma unroll
            for (int ks = 0; ks < 64; ks += 16) {
                unsigned ah[2][4], al[2][4];
#pragma unroll
                for (int mt = 0; mt < 2; ++mt) {
                    int r0 = (wm * 32 + mt * 16 + g) * ASTRIDE + ks + t * 2;
                    int r1 = r0 + 8 * ASTRIDE;
                    ah[mt][0] = lds32(sAh + r0);
                    ah[mt][1] = lds32(sAh + r1);
                    ah[mt][2] = lds32(sAh + r0 + 8);
                    ah[mt][3] = lds32(sAh + r1 + 8);
                    al[mt][0] = lds32(sAl + r0);
                    al[mt][1] = lds32(sAl + r1);
                    al[mt][2] = lds32(sAl + r0 + 8);
                    al[mt][3] = lds32(sAl + r1 + 8);
                }
#pragma unroll
                for (int e = 0; e < 3; ++e) {
                    unsigned bh[4][2], bl[4][2];
#pragma unroll
                    for (int nt = 0; nt < 4; ++nt) {
                        int c0 = (e * 64 + wn * 32 + nt * 8 + g) * ASTRIDE + ks + t * 2;
                        bh[nt][0] = lds32(sWh + c0);
                        bh[nt][1] = lds32(sWh + c0 + 8);
                        bl[nt][0] = lds32(sWl + c0);
                        bl[nt][1] = lds32(sWl + c0 + 8);
                    }
#pragma unroll
                    for (int mt = 0; mt < 2; ++mt)
#pragma unroll
                        for (int nt = 0; nt < 4; ++nt) {
                            mma16816(acc[e][mt][nt], ah[mt], bh[nt]);
                            mma16816(acc[e][mt][nt], ah[mt], bl[nt]);
                            mma16816(acc[e][mt][nt], al[mt], bh[nt]);
                        }
                }
            }
            buf ^= 1;
            __syncthreads();
        }

        // ---------------- epilogue (register-only operands) ----------------
#pragma unroll
        for (int mt = 0; mt < 2; ++mt)
#pragma unroll
            for (int h = 0; h < 2; ++h) {
                int m = m0 + wm * 32 + mt * 16 + g + h * 8;
                float ga = gv[mt][h][0], gb = gv[mt][h][1], gc = gv[mt][h][2];
#pragma unroll
                for (int nt = 0; nt < 4; ++nt) {
                    int n = n0 + wn * 32 + nt * 8 + t * 2;
                    float v0 = ga * (acc[0][mt][nt][h * 2 + 0] + bb[0][nt][0])
                             + gb * (acc[1][mt][nt][h * 2 + 0] + bb[1][nt][0])
                             + gc * (acc[2][mt][nt][h * 2 + 0] + bb[2][nt][0]);
                    float v1 = ga * (acc[0][mt][nt][h * 2 + 1] + bb[0][nt][1])
                             + gb * (acc[1][mt][nt][h * 2 + 1] + bb[1][nt][1])
                             + gc * (acc[2][mt][nt][h * 2 + 1] + bb[2][nt][1]);
                    if (RELU) { v0 = fmaxf(v0, 0.f); v1 = fmaxf(v1, 0.f); }
                    if (FP32OUT) {
                        float2 o = {v0, v1};
                        *reinterpret_cast<float2*>(&Ofp[(size_t)m * NOUT + n]) = o;
                    } else {
                        __nv_bfloat16 h0, h1, l0, l1;
                        split_hilo(v0, h0, l0);
                        split_hilo(v1, h1, l1);
                        *reinterpret_cast<__nv_bfloat162*>(&Ohi[(size_t)m * NOUT + n]) = __nv_bfloat162{h0, h1};
                        *reinterpret_cast<__nv_bfloat162*>(&Olo[(size_t)m * NOUT + n]) = __nv_bfloat162{l0, l1};
                    }
                }
            }

        tile += stride;
    }
}

// ---------------------------------------------------------------------------
// Launch
// ---------------------------------------------------------------------------
extern "C" void kernel_launch(void* const* d_in, const int* in_sizes, int n_in,
                              void* d_out, int out_size)
{
    const float* f1  = (const float*)d_in[0];
    const float* f2  = (const float*)d_in[1];
    const float* lat = (const float*)d_in[2];
    const float* g0w = (const float*)d_in[3];
    const float* g0b = (const float*)d_in[4];
    const float* g1w = (const float*)d_in[5];
    const float* g1b = (const float*)d_in[6];
    const float* g2w = (const float*)d_in[7];
    const float* g2b = (const float*)d_in[8];
    const float* W1  = (const float*)d_in[9];
    const float* b1  = (const float*)d_in[10];
    const float* W2  = (const float*)d_in[11];
    const float* b2  = (const float*)d_in[12];
    const float* W3  = (const float*)d_in[13];
    const float* b3  = (const float*)d_in[14];
    const float* W4  = (const float*)d_in[15];
    const float* b4  = (const float*)d_in[16];

    float* out      = (float*)d_out;
    float* gate_out = out + (size_t)B_ROWS * LATD;

    __nv_bfloat16 *w1hi, *w1lo, *w2hi, *w2lo, *w3hi, *w3lo, *w4hi, *w4lo;
    __nv_bfloat16 *xhi, *xlo, *h1hi, *h1lo, *h2hi, *h2lo;
    cudaGetSymbolAddress((void**)&w1hi, g_w1hi); cudaGetSymbolAddress((void**)&w1lo, g_w1lo);
    cudaGetSymbolAddress((void**)&w2hi, g_w2hi); cudaGetSymbolAddress((void**)&w2lo, g_w2lo);
    cudaGetSymbolAddress((void**)&w3hi, g_w3hi); cudaGetSymbolAddress((void**)&w3lo, g_w3lo);
    cudaGetSymbolAddress((void**)&w4hi, g_w4hi); cudaGetSymbolAddress((void**)&w4lo, g_w4lo);
    cudaGetSymbolAddress((void**)&xhi,  g_xhi);  cudaGetSymbolAddress((void**)&xlo,  g_xlo);
    cudaGetSymbolAddress((void**)&h1hi, g_h1hi); cudaGetSymbolAddress((void**)&h1lo, g_h1lo);
    cudaGetSymbolAddress((void**)&h2hi, g_h2hi); cudaGetSymbolAddress((void**)&h2lo, g_h2lo);

    int nsm = 148;
    cudaDeviceGetAttribute(&nsm, cudaDevAttrMultiProcessorCount, 0);

    // conversions
    {
        int n4 = NE * HID * NIN / 4;
        convert_hilo<<<(n4 + 255) / 256, 256>>>(W1, w1hi, w1lo, n4);
        n4 = NE * HID * HID / 4;
        convert_hilo<<<(n4 + 255) / 256, 256>>>(W2, w2hi, w2lo, n4);
        convert_hilo<<<(n4 + 255) / 256, 256>>>(W3, w3hi, w3lo, n4);
        n4 = NE * LATD * HID / 4;
        convert_hilo<<<(n4 + 255) / 256, 256>>>(W4, w4hi, w4lo, n4);
        int nx = B_ROWS * (NIN / 4);
        xprep_kernel<<<nx / 256, 256>>>(f1, f2, lat);
    }

    // gate path
    gate0_kernel<<<B_ROWS / 256, 256>>>(f1, f2, lat, g0w, g0b);
    gate1_kernel<<<B_ROWS / 256, 256>>>(g1w, g1b, g2w, g2b, gate_out);

    // blend layers — persistent grid, dynamic smem (2 stages of 92160B)
    constexpr int SMEM_BYTES = 2 * STAGE_U * 2;   // 184320

    cudaFuncSetAttribute(blend_mma<NIN, HID, true, false>,
                         cudaFuncAttributeMaxDynamicSharedMemorySize, SMEM_BYTES);
    cudaFuncSetAttribute(blend_mma<HID, HID, true, false>,
                         cudaFuncAttributeMaxDynamicSharedMemorySize, SMEM_BYTES);
    cudaFuncSetAttribute(blend_mma<HID, LATD, false, true>,
                         cudaFuncAttributeMaxDynamicSharedMemorySize, SMEM_BYTES);

    blend_mma<NIN, HID, true, false><<<nsm, 256, SMEM_BYTES>>>(
        xhi, xlo, w1hi, w1lo, b1, h1hi, h1lo, nullptr);
    blend_mma<HID, HID, true, false><<<nsm, 256, SMEM_BYTES>>>(
        h1hi, h1lo, w2hi, w2lo, b2, h2hi, h2lo, nullptr);
    blend_mma<HID, HID, true, false><<<nsm, 256, SMEM_BYTES>>>(
        h2hi, h2lo, w3hi, w3lo, b3, h1hi, h1lo, nullptr);
    blend_mma<HID, LATD, false, true><<<nsm, 256, SMEM_BYTES>>>(
        h1hi, h1lo, w4hi, w4lo, b4, nullptr, nullptr, out);
}

// round 9
// speedup vs baseline: 1.5342x; 1.3688x over previous
#include <cuda_runtime.h>
#include <cuda_bf16.h>
#include <cuda_fp16.h>
#include <math.h>
#include <stdint.h>

// Problem constants
#define B_ROWS 131072
#define FEAT 256
#define LATD 128
#define NIN 640           // 2*FEAT + LATD
#define HG 32
#define HID 512
#define NE 3

// ---------------------------------------------------------------------------
// Scratch (device globals — no runtime allocation allowed)
// ---------------------------------------------------------------------------
__device__ float g_u[(size_t)B_ROWS * HG];
__device__ float g_gate[(size_t)B_ROWS * NE];

// single-plane fp16 activations
__device__ __half g_x[(size_t)B_ROWS * NIN];
__device__ __half g_h1[(size_t)B_ROWS * HID];
__device__ __half g_h2[(size_t)B_ROWS * HID];

// fp16 hi/lo weight planes
__device__ __half g_w1hi[NE * HID * NIN];
__device__ __half g_w1lo[NE * HID * NIN];
__device__ __half g_w2hi[NE * HID * HID];
__device__ __half g_w2lo[NE * HID * HID];
__device__ __half g_w3hi[NE * HID * HID];
__device__ __half g_w3lo[NE * HID * HID];
__device__ __half g_w4hi[NE * LATD * HID];
__device__ __half g_w4lo[NE * LATD * HID];

// ---------------------------------------------------------------------------
// helpers
// ---------------------------------------------------------------------------
__device__ __forceinline__ uint32_t smem_u32(const void* p) {
    uint32_t a;
    asm("{ .reg .u64 t; cvta.to.shared.u64 t, %1; cvt.u32.u64 %0, t; }" : "=r"(a) : "l"(p));
    return a;
}

#define CP_ASYNC16(dst, src) \
    asm volatile("cp.async.cg.shared.global [%0], [%1], 16;" :: "r"(dst), "l"(src))
#define CP_COMMIT() asm volatile("cp.async.commit_group;" ::: "memory")
#define CP_WAIT0()  asm volatile("cp.async.wait_group 0;" ::: "memory")
#define CP_WAIT1()  asm volatile("cp.async.wait_group 1;" ::: "memory")

__device__ __forceinline__ void split_hilo_h(float v, __half& h, __half& l) {
    h = __float2half_rn(v);
    l = __float2half_rn(v - __half2float(h));
}

__device__ __forceinline__ void mma16816h(float* c, const unsigned* a, const unsigned* b) {
    asm volatile(
        "mma.sync.aligned.m16n8k16.row.col.f32.f16.f16.f32 "
        "{%0,%1,%2,%3}, {%4,%5,%6,%7}, {%8,%9}, {%0,%1,%2,%3};\n"
        : "+f"(c[0]), "+f"(c[1]), "+f"(c[2]), "+f"(c[3])
        : "r"(a[0]), "r"(a[1]), "r"(a[2]), "r"(a[3]), "r"(b[0]), "r"(b[1]));
}

__device__ __forceinline__ unsigned lds32h(const __half* p) {
    return *reinterpret_cast<const unsigned*>(p);
}

// ---------------------------------------------------------------------------
// prep kernels
// ---------------------------------------------------------------------------
__global__ __launch_bounds__(256) void convert_hilo_h(
    const float* __restrict__ src, __half* __restrict__ hi,
    __half* __restrict__ lo, int n4)
{
    int i = blockIdx.x * blockDim.x + threadIdx.x;
    if (i >= n4) return;
    float4 v = reinterpret_cast<const float4*>(src)[i];
    __half h0, h1, h2, h3, l0, l1, l2, l3;
    split_hilo_h(v.x, h0, l0); split_hilo_h(v.y, h1, l1);
    split_hilo_h(v.z, h2, l2); split_hilo_h(v.w, h3, l3);
    __half2* hp = reinterpret_cast<__half2*>(hi) + i * 2;
    __half2* lp = reinterpret_cast<__half2*>(lo) + i * 2;
    hp[0] = __half2{h0, h1}; hp[1] = __half2{h2, h3};
    lp[0] = __half2{l0, l1}; lp[1] = __half2{l2, l3};
}

__global__ __launch_bounds__(256) void xprep_kernel(
    const float* __restrict__ f1, const float* __restrict__ f2,
    const float* __restrict__ lat)
{
    int i = blockIdx.x * blockDim.x + threadIdx.x;
    int row = i / (NIN / 4);
    int kk = (i % (NIN / 4)) * 4;
    float4 v;
    if (kk < FEAT)
        v = *reinterpret_cast<const float4*>(&f1[(size_t)row * FEAT + kk]);
    else if (kk < 2 * FEAT)
        v = *reinterpret_cast<const float4*>(&f2[(size_t)row * FEAT + kk - FEAT]);
    else
        v = *reinterpret_cast<const float4*>(&lat[(size_t)row * LATD + kk - 2 * FEAT]);
    size_t base = (size_t)row * NIN + kk;
    *reinterpret_cast<__half2*>(&g_x[base]) =
        __half2{__float2half_rn(v.x), __float2half_rn(v.y)};
    *reinterpret_cast<__half2*>(&g_x[base + 2]) =
        __half2{__float2half_rn(v.z), __float2half_rn(v.w)};
}

__global__ __launch_bounds__(256) void gate0_kernel(
    const float* __restrict__ f1, const float* __restrict__ f2,
    const float* __restrict__ lat,
    const float* __restrict__ w, const float* __restrict__ bias)
{
    __shared__ float As[16][260];
    __shared__ float Ws[16][36];

    const int tid = threadIdx.x;
    const int tx = tid & 7;
    const int ty = tid >> 3;
    const int m0 = blockIdx.x * 256;

    float acc[8][4];
#pragma unroll
    for (int i = 0; i < 8; ++i)
#pragma unroll
        for (int j = 0; j < 4; ++j) acc[i][j] = 0.f;

    for (int k0 = 0; k0 < NIN; k0 += 16) {
#pragma unroll
        for (int r = 0; r < 4; ++r) {
            int idx = r * 256 + tid;
            int m = idx >> 2;
            int kq = (idx & 3) * 4;
            int kg = k0 + kq;
            float4 v;
            if (kg < FEAT)
                v = *reinterpret_cast<const float4*>(&f1[(size_t)(m0 + m) * FEAT + kg]);
            else if (kg < 2 * FEAT)
                v = *reinterpret_cast<const float4*>(&f2[(size_t)(m0 + m) * FEAT + (kg - FEAT)]);
            else
                v = *reinterpret_cast<const float4*>(&lat[(size_t)(m0 + m) * LATD + (kg - 2 * FEAT)]);
            As[kq + 0][m] = v.x; As[kq + 1][m] = v.y;
            As[kq + 2][m] = v.z; As[kq + 3][m] = v.w;
        }
        if (tid < 128) {
            int n = tid >> 2;
            int kq = (tid & 3) * 4;
            float4 v = *reinterpret_cast<const float4*>(&w[(size_t)n * NIN + k0 + kq]);
            Ws[kq + 0][n] = v.x; Ws[kq + 1][n] = v.y;
            Ws[kq + 2][n] = v.z; Ws[kq + 3][n] = v.w;
        }
        __syncthreads();
#pragma unroll
        for (int k = 0; k < 16; ++k) {
            const float4 a0 = *reinterpret_cast<const float4*>(&As[k][ty * 8]);
            const float4 a1 = *reinterpret_cast<const float4*>(&As[k][ty * 8 + 4]);
            const float4 b  = *reinterpret_cast<const float4*>(&Ws[k][tx * 4]);
            float av[8] = {a0.x, a0.y, a0.z, a0.w, a1.x, a1.y, a1.z, a1.w};
            float bv[4] = {b.x, b.y, b.z, b.w};
#pragma unroll
            for (int i = 0; i < 8; ++i)
#pragma unroll
                for (int j = 0; j < 4; ++j)
                    acc[i][j] = fmaf(av[i], bv[j], acc[i][j]);
        }
        __syncthreads();
    }

    float bb[4];
#pragma unroll
    for (int j = 0; j < 4; ++j) bb[j] = bias[tx * 4 + j];
#pragma unroll
    for (int i = 0; i < 8; ++i) {
        int m = m0 + ty * 8 + i;
        float4 o;
        o.x = acc[i][0] + bb[0];
        o.y = acc[i][1] + bb[1];
        o.z = acc[i][2] + bb[2];
        o.w = acc[i][3] + bb[3];
        *reinterpret_cast<float4*>(&g_u[(size_t)m * HG + tx * 4]) = o;
    }
}

__global__ __launch_bounds__(256) void gate1_kernel(
    const float* __restrict__ g1w, const float* __restrict__ g1b,
    const float* __restrict__ g2w, const float* __restrict__ g2b,
    float* __restrict__ out_gate)
{
    __shared__ float us[256][33];
    __shared__ float w1s[32][33];
    __shared__ float b1s[32];
    __shared__ float w2s[3][32];
    __shared__ float b2s[3];

    const int tid = threadIdx.x;
    const int m0 = blockIdx.x * 256;

    for (int idx = tid; idx < 256 * 32; idx += 256) {
        int r = idx >> 5, c = idx & 31;
        us[r][c] = g_u[(size_t)(m0 + r) * HG + c];
    }
    for (int idx = tid; idx < 32 * 32; idx += 256)
        w1s[idx >> 5][idx & 31] = g1w[idx];
    if (tid < 32) b1s[tid] = g1b[tid];
    if (tid < 96) w2s[tid / 32][tid % 32] = g2w[tid];
    if (tid < 3) b2s[tid] = g2b[tid];
    __syncthreads();

    const int m = m0 + tid;

    float eu[32];
#pragma unroll
    for (int k = 0; k < 32; ++k) {
        float x = us[tid][k];
        eu[k] = (x > 0.f) ? x : expm1f(x);
    }
    float ev[32];
#pragma unroll
    for (int j = 0; j < 32; ++j) {
        float v = b1s[j];
#pragma unroll
        for (int k = 0; k < 32; ++k) v = fmaf(eu[k], w1s[j][k], v);
        ev[j] = (v > 0.f) ? v : expm1f(v);
    }
    float s[3];
#pragma unroll
    for (int e = 0; e < 3; ++e) {
        float v = b2s[e];
#pragma unroll
        for (int j = 0; j < 32; ++j) v = fmaf(ev[j], w2s[e][j], v);
        s[e] = v;
    }
    float mx = fmaxf(s[0], fmaxf(s[1], s[2]));
    float p0 = expf(s[0] - mx);
    float p1 = expf(s[1] - mx);
    float p2 = expf(s[2] - mx);
    float inv = 1.f / (p0 + p1 + p2);
    p0 *= inv; p1 *= inv; p2 *= inv;

    g_gate[(size_t)m * 3 + 0] = p0;
    g_gate[(size_t)m * 3 + 1] = p1;
    g_gate[(size_t)m * 3 + 2] = p2;
    out_gate[(size_t)m * 3 + 0] = p0;
    out_gate[(size_t)m * 3 + 1] = p1;
    out_gate[(size_t)m * 3 + 2] = p2;
}

// ---------------------------------------------------------------------------
// blend_mma v5: fp16 2-term (a*wh + a*wl), persistent CTAs, cp.async pipeline.
// Out[m,n] = act( sum_e gate[m,e] * ((A @ W_e^T)[m,n] + b_e[n]) )
// A single fp16 plane; W fp16 hi+lo. fp32 accumulate.
// Block tile: M=128 x N=64 x E=3, 8 warps (warp tile 32x32 per expert).
//
// smem per stage (half units, row stride 72):
//   A 128*72 | W hi 192*72 | W lo 192*72  = 36864 units (73728B)
// ---------------------------------------------------------------------------
#define ASTRIDE 72
#define AROWS 128
#define WROWS 192
#define STAGE_U ((AROWS + 2 * WROWS) * ASTRIDE)   // 36864 half units

template <int KDIM, int NOUT>
__device__ __forceinline__ void prefetch_chunk(
    __half* sm, int stage, int k0, int m0, int n0,
    const __half* __restrict__ A,
    const __half* __restrict__ Whi, const __half* __restrict__ Wlo)
{
    const int tid = threadIdx.x;
    const uint32_t base = smem_u32(sm) + (uint32_t)stage * STAGE_U * 2;
    // A: 128 rows * 8 = 1024 chunks ; W: 2 planes * 192 rows * 8 = 3072 chunks
#pragma unroll
    for (int it = 0; it < 16; ++it) {
        int i = tid + it * 256;               // 0..4095
        uint32_t dst;
        const __half* src;
        if (i < 1024) {
            int row = i >> 3, c = i & 7;
            src = A + (size_t)(m0 + row) * KDIM + k0 + c * 8;
            dst = base + (uint32_t)(row * ASTRIDE + c * 8) * 2;
        } else {
            int j = i - 1024;                 // 0..3071
            int plane = j >= 1536;
            int idx = j - plane * 1536;
            int r = idx >> 3, c = idx & 7;    // r in [0,192)
            int e = r >> 6, n = r & 63;
            const __half* Wp = plane ? Wlo : Whi;
            src = Wp + ((size_t)e * NOUT + n0 + n) * KDIM + k0 + c * 8;
            dst = base + (uint32_t)(AROWS * ASTRIDE + plane * WROWS * ASTRIDE +
                                    r * ASTRIDE + c * 8) * 2;
        }
        CP_ASYNC16(dst, src);
    }
}

template <int KDIM, int NOUT, bool RELU, bool FP32OUT>
__global__ __launch_bounds__(256, 1) void blend_mma(
    const __half* __restrict__ A,
    const __half* __restrict__ Whi, const __half* __restrict__ Wlo,
    const float* __restrict__ bias,
    __half* __restrict__ Oh, float* __restrict__ Ofp)
{
    extern __shared__ __half smbuf[];

    constexpr int NTN = NOUT / 64;            // n-tiles
    constexpr int NT = (B_ROWS / 128) * NTN;  // total tiles
    constexpr int NCH = KDIM / 64;

    const int tid = threadIdx.x;
    const int w = tid >> 5, lane = tid & 31;
    const int wm = w & 3, wn = w >> 2;        // warps: 4 along M, 2 along N
    const int g = lane >> 2, t = lane & 3;
    const int stride = gridDim.x;

    int tile = blockIdx.x;
    if (tile >= NT) return;

    {
        int m0 = (tile / NTN) * 128, n0 = (tile % NTN) * 64;
        prefetch_chunk<KDIM, NOUT>(smbuf, 0, 0, m0, n0, A, Whi, Wlo);
        CP_COMMIT();
    }
    int buf = 0;

    while (tile < NT) {
        const int m0 = (tile / NTN) * 128;
        const int n0 = (tile % NTN) * 64;

        float gv[2][2][3];
#pragma unroll
        for (int mt = 0; mt < 2; ++mt)
#pragma unroll
            for (int h = 0; h < 2; ++h) {
                int m = m0 + wm * 32 + mt * 16 + g + h * 8;
                gv[mt][h][0] = g_gate[(size_t)m * 3 + 0];
                gv[mt][h][1] = g_gate[(size_t)m * 3 + 1];
                gv[mt][h][2] = g_gate[(size_t)m * 3 + 2];
            }
        float bb[3][4][2];
#pragma unroll
        for (int e = 0; e < 3; ++e)
#pragma unroll
            for (int nt = 0; nt < 4; ++nt) {
                int n = n0 + wn * 32 + nt * 8 + t * 2;
                bb[e][nt][0] = bias[e * NOUT + n];
                bb[e][nt][1] = bias[e * NOUT + n + 1];
            }

        float acc[3][2][4][4];
#pragma unroll
        for (int e = 0; e < 3; ++e)
#pragma unroll
            for (int mt = 0; mt < 2; ++mt)
#pragma unroll
                for (int nt = 0; nt < 4; ++nt)
#pragma unroll
                    for (int c = 0; c < 4; ++c) acc[e][mt][nt][c] = 0.f;

        for (int ch = 0; ch < NCH; ++ch) {
            int ntile, nch;
            if (ch + 1 < NCH) { ntile = tile; nch = ch + 1; }
            else { ntile = tile + stride; nch = 0; }
            if (ntile < NT) {
                int nm0 = (ntile / NTN) * 128, nn0 = (ntile % NTN) * 64;
                prefetch_chunk<KDIM, NOUT>(smbuf, buf ^ 1, nch * 64, nm0, nn0,
                                           A, Whi, Wlo);
                CP_COMMIT();
                CP_WAIT1();
            } else {
                CP_WAIT0();
            }
            __syncthreads();

            const __half* sA  = smbuf + buf * STAGE_U;
            const __half* sWh = sA + AROWS * ASTRIDE;
            const __half* sWl = sWh + WROWS * ASTRIDE;

#pragma unroll
            for (int ks = 0; ks < 64; ks += 16) {
                unsigned a[2][4];
#pragma unroll
                for (int mt = 0; mt < 2; ++mt) {
                    int r0 = (wm * 32 + mt * 16 + g) * ASTRIDE + ks + t * 2;
                    int r1 = r0 + 8 * ASTRIDE;
                    a[mt][0] = lds32h(sA + r0);
                    a[mt][1] = lds32h(sA + r1);
                    a[mt][2] = lds32h(sA + r0 + 8);
                    a[mt][3] = lds32h(sA + r1 + 8);
                }
#pragma unroll
                for (int e = 0; e < 3; ++e) {
                    unsigned bh[4][2], bl[4][2];
#pragma unroll
                    for (int nt = 0; nt < 4; ++nt) {
                        int c0 = (e * 64 + wn * 32 + nt * 8 + g) * ASTRIDE + ks + t * 2;
                        bh[nt][0] = lds32h(sWh + c0);
                        bh[nt][1] = lds32h(sWh + c0 + 8);
                        bl[nt][0] = lds32h(sWl + c0);
                        bl[nt][1] = lds32h(sWl + c0 + 8);
                    }
#pragma unroll
                    for (int mt = 0; mt < 2; ++mt)
#pragma unroll
                        for (int nt = 0; nt < 4; ++nt) {
                            mma16816h(acc[e][mt][nt], a[mt], bh[nt]);
                            mma16816h(acc[e][mt][nt], a[mt], bl[nt]);
                        }
                }
            }
            buf ^= 1;
            __syncthreads();
        }

        // ---------------- epilogue (register-only operands) ----------------
#pragma unroll
        for (int mt = 0; mt < 2; ++mt)
#pragma unroll
            for (int h = 0; h < 2; ++h) {
                int m = m0 + wm * 32 + mt * 16 + g + h * 8;
                float ga = gv[mt][h][0], gb = gv[mt][h][1], gc = gv[mt][h][2];
#pragma unroll
                for (int nt = 0; nt < 4; ++nt) {
                    int n = n0 + wn * 32 + nt * 8 + t * 2;
                    float v0 = ga * (acc[0][mt][nt][h * 2 + 0] + bb[0][nt][0])
                             + gb * (acc[1][mt][nt][h * 2 + 0] + bb[1][nt][0])
                             + gc * (acc[2][mt][nt][h * 2 + 0] + bb[2][nt][0]);
                    float v1 = ga * (acc[0][mt][nt][h * 2 + 1] + bb[0][nt][1])
                             + gb * (acc[1][mt][nt][h * 2 + 1] + bb[1][nt][1])
                             + gc * (acc[2][mt][nt][h * 2 + 1] + bb[2][nt][1]);
                    if (RELU) { v0 = fmaxf(v0, 0.f); v1 = fmaxf(v1, 0.f); }
                    if (FP32OUT) {
                        float2 o = {v0, v1};
                        *reinterpret_cast<float2*>(&Ofp[(size_t)m * NOUT + n]) = o;
                    } else {
                        *reinterpret_cast<__half2*>(&Oh[(size_t)m * NOUT + n]) =
                            __half2{__float2half_rn(v0), __float2half_rn(v1)};
                    }
                }
            }

        tile += stride;
    }
}

// ---------------------------------------------------------------------------
// Launch
// ---------------------------------------------------------------------------
extern "C" void kernel_launch(void* const* d_in, const int* in_sizes, int n_in,
                              void* d_out, int out_size)
{
    const float* f1  = (const float*)d_in[0];
    const float* f2  = (const float*)d_in[1];
    const float* lat = (const float*)d_in[2];
    const float* g0w = (const float*)d_in[3];
    const float* g0b = (const float*)d_in[4];
    const float* g1w = (const float*)d_in[5];
    const float* g1b = (const float*)d_in[6];
    const float* g2w = (const float*)d_in[7];
    const float* g2b = (const float*)d_in[8];
    const float* W1  = (const float*)d_in[9];
    const float* b1  = (const float*)d_in[10];
    const float* W2  = (const float*)d_in[11];
    const float* b2  = (const float*)d_in[12];
    const float* W3  = (const float*)d_in[13];
    const float* b3  = (const float*)d_in[14];
    const float* W4  = (const float*)d_in[15];
    const float* b4  = (const float*)d_in[16];

    float* out      = (float*)d_out;
    float* gate_out = out + (size_t)B_ROWS * LATD;

    __half *w1hi, *w1lo, *w2hi, *w2lo, *w3hi, *w3lo, *w4hi, *w4lo;
    __half *x, *h1, *h2;
    cudaGetSymbolAddress((void**)&w1hi, g_w1hi); cudaGetSymbolAddress((void**)&w1lo, g_w1lo);
    cudaGetSymbolAddress((void**)&w2hi, g_w2hi); cudaGetSymbolAddress((void**)&w2lo, g_w2lo);
    cudaGetSymbolAddress((void**)&w3hi, g_w3hi); cudaGetSymbolAddress((void**)&w3lo, g_w3lo);
    cudaGetSymbolAddress((void**)&w4hi, g_w4hi); cudaGetSymbolAddress((void**)&w4lo, g_w4lo);
    cudaGetSymbolAddress((void**)&x,  g_x);
    cudaGetSymbolAddress((void**)&h1, g_h1);
    cudaGetSymbolAddress((void**)&h2, g_h2);

    int nsm = 148;
    cudaDeviceGetAttribute(&nsm, cudaDevAttrMultiProcessorCount, 0);

    // conversions
    {
        int n4 = NE * HID * NIN / 4;
        convert_hilo_h<<<(n4 + 255) / 256, 256>>>(W1, w1hi, w1lo, n4);
        n4 = NE * HID * HID / 4;
        convert_hilo_h<<<(n4 + 255) / 256, 256>>>(W2, w2hi, w2lo, n4);
        convert_hilo_h<<<(n4 + 255) / 256, 256>>>(W3, w3hi, w3lo, n4);
        n4 = NE * LATD * HID / 4;
        convert_hilo_h<<<(n4 + 255) / 256, 256>>>(W4, w4hi, w4lo, n4);
        int nx = B_ROWS * (NIN / 4);
        xprep_kernel<<<nx / 256, 256>>>(f1, f2, lat);
    }

    // gate path
    gate0_kernel<<<B_ROWS / 256, 256>>>(f1, f2, lat, g0w, g0b);
    gate1_kernel<<<B_ROWS / 256, 256>>>(g1w, g1b, g2w, g2b, gate_out);

    // blend layers — persistent grid, dynamic smem (2 stages of 73728B)
    constexpr int SMEM_BYTES = 2 * STAGE_U * 2;   // 147456

    cudaFuncSetAttribute(blend_mma<NIN, HID, true, false>,
                         cudaFuncAttributeMaxDynamicSharedMemorySize, SMEM_BYTES);
    cudaFuncSetAttribute(blend_mma<HID, HID, true, false>,
                         cudaFuncAttributeMaxDynamicSharedMemorySize, SMEM_BYTES);
    cudaFuncSetAttribute(blend_mma<HID, LATD, false, true>,
                         cudaFuncAttributeMaxDynamicSharedMemorySize, SMEM_BYTES);

    blend_mma<NIN, HID, true, false><<<nsm, 256, SMEM_BYTES>>>(
        x, w1hi, w1lo, b1, h1, nullptr);
    blend_mma<HID, HID, true, false><<<nsm, 256, SMEM_BYTES>>>(
        h1, w2hi, w2lo, b2, h2, nullptr);
    blend_mma<HID, HID, true, false><<<nsm, 256, SMEM_BYTES>>>(
        h2, w3hi, w3lo, b3, h1, nullptr);
    blend_mma<HID, LATD, false, true><<<nsm, 256, SMEM_BYTES>>>(
        h1, w4hi, w4lo, b4, nullptr, out);
}

// round 10
// speedup vs baseline: 2.4378x; 1.5889x over previous
#include <cuda_runtime.h>
#include <cuda_bf16.h>
#include <cuda_fp16.h>
#include <math.h>
#include <stdint.h>

// Problem constants
#define B_ROWS 131072
#define FEAT 256
#define LATD 128
#define NIN 640           // 2*FEAT + LATD
#define HG 32
#define HID 512
#define NE 3

// ---------------------------------------------------------------------------
// Scratch (device globals — no runtime allocation allowed)
// ---------------------------------------------------------------------------
__device__ float g_u[(size_t)B_ROWS * HG];
__device__ float g_gate[(size_t)B_ROWS * NE];

// single-plane fp16 activations
__device__ __half g_x[(size_t)B_ROWS * NIN];
__device__ __half g_h1[(size_t)B_ROWS * HID];
__device__ __half g_h2[(size_t)B_ROWS * HID];

// single-plane fp16 weights
__device__ __half g_w1[NE * HID * NIN];
__device__ __half g_w2[NE * HID * HID];
__device__ __half g_w3[NE * HID * HID];
__device__ __half g_w4[NE * LATD * HID];

// ---------------------------------------------------------------------------
// helpers
// ---------------------------------------------------------------------------
__device__ __forceinline__ uint32_t smem_u32(const void* p) {
    uint32_t a;
    asm("{ .reg .u64 t; cvta.to.shared.u64 t, %1; cvt.u32.u64 %0, t; }" : "=r"(a) : "l"(p));
    return a;
}

#define CP_ASYNC16(dst, src) \
    asm volatile("cp.async.cg.shared.global [%0], [%1], 16;" :: "r"(dst), "l"(src))
#define CP_COMMIT() asm volatile("cp.async.commit_group;" ::: "memory")
#define CP_WAIT0()  asm volatile("cp.async.wait_group 0;" ::: "memory")
#define CP_WAIT1()  asm volatile("cp.async.wait_group 1;" ::: "memory")

__device__ __forceinline__ void mma16816h(float* c, const unsigned* a, const unsigned* b) {
    asm volatile(
        "mma.sync.aligned.m16n8k16.row.col.f32.f16.f16.f32 "
        "{%0,%1,%2,%3}, {%4,%5,%6,%7}, {%8,%9}, {%0,%1,%2,%3};\n"
        : "+f"(c[0]), "+f"(c[1]), "+f"(c[2]), "+f"(c[3])
        : "r"(a[0]), "r"(a[1]), "r"(a[2]), "r"(a[3]), "r"(b[0]), "r"(b[1]));
}

__device__ __forceinline__ unsigned lds32h(const __half* p) {
    return *reinterpret_cast<const unsigned*>(p);
}

// ---------------------------------------------------------------------------
// prep kernels
// ---------------------------------------------------------------------------
__global__ __launch_bounds__(256) void convert_h(
    const float* __restrict__ src, __half* __restrict__ dst, int n4)
{
    int i = blockIdx.x * blockDim.x + threadIdx.x;
    if (i >= n4) return;
    float4 v = reinterpret_cast<const float4*>(src)[i];
    __half2* dp = reinterpret_cast<__half2*>(dst) + i * 2;
    dp[0] = __half2{__float2half_rn(v.x), __float2half_rn(v.y)};
    dp[1] = __half2{__float2half_rn(v.z), __float2half_rn(v.w)};
}

__global__ __launch_bounds__(256) void xprep_kernel(
    const float* __restrict__ f1, const float* __restrict__ f2,
    const float* __restrict__ lat)
{
    int i = blockIdx.x * blockDim.x + threadIdx.x;
    int row = i / (NIN / 4);
    int kk = (i % (NIN / 4)) * 4;
    float4 v;
    if (kk < FEAT)
        v = *reinterpret_cast<const float4*>(&f1[(size_t)row * FEAT + kk]);
    else if (kk < 2 * FEAT)
        v = *reinterpret_cast<const float4*>(&f2[(size_t)row * FEAT + kk - FEAT]);
    else
        v = *reinterpret_cast<const float4*>(&lat[(size_t)row * LATD + kk - 2 * FEAT]);
    size_t base = (size_t)row * NIN + kk;
    *reinterpret_cast<__half2*>(&g_x[base]) =
        __half2{__float2half_rn(v.x), __float2half_rn(v.y)};
    *reinterpret_cast<__half2*>(&g_x[base + 2]) =
        __half2{__float2half_rn(v.z), __float2half_rn(v.w)};
}

__global__ __launch_bounds__(256) void gate0_kernel(
    const float* __restrict__ f1, const float* __restrict__ f2,
    const float* __restrict__ lat,
    const float* __restrict__ w, const float* __restrict__ bias)
{
    __shared__ float As[16][260];
    __shared__ float Ws[16][36];

    const int tid = threadIdx.x;
    const int tx = tid & 7;
    const int ty = tid >> 3;
    const int m0 = blockIdx.x * 256;

    float acc[8][4];
#pragma unroll
    for (int i = 0; i < 8; ++i)
#pragma unroll
        for (int j = 0; j < 4; ++j) acc[i][j] = 0.f;

    for (int k0 = 0; k0 < NIN; k0 += 16) {
#pragma unroll
        for (int r = 0; r < 4; ++r) {
            int idx = r * 256 + tid;
            int m = idx >> 2;
            int kq = (idx & 3) * 4;
            int kg = k0 + kq;
            float4 v;
            if (kg < FEAT)
                v = *reinterpret_cast<const float4*>(&f1[(size_t)(m0 + m) * FEAT + kg]);
            else if (kg < 2 * FEAT)
                v = *reinterpret_cast<const float4*>(&f2[(size_t)(m0 + m) * FEAT + (kg - FEAT)]);
            else
                v = *reinterpret_cast<const float4*>(&lat[(size_t)(m0 + m) * LATD + (kg - 2 * FEAT)]);
            As[kq + 0][m] = v.x; As[kq + 1][m] = v.y;
            As[kq + 2][m] = v.z; As[kq + 3][m] = v.w;
        }
        if (tid < 128) {
            int n = tid >> 2;
            int kq = (tid & 3) * 4;
            float4 v = *reinterpret_cast<const float4*>(&w[(size_t)n * NIN + k0 + kq]);
            Ws[kq + 0][n] = v.x; Ws[kq + 1][n] = v.y;
            Ws[kq + 2][n] = v.z; Ws[kq + 3][n] = v.w;
        }
        __syncthreads();
#pragma unroll
        for (int k = 0; k < 16; ++k) {
            const float4 a0 = *reinterpret_cast<const float4*>(&As[k][ty * 8]);
            const float4 a1 = *reinterpret_cast<const float4*>(&As[k][ty * 8 + 4]);
            const float4 b  = *reinterpret_cast<const float4*>(&Ws[k][tx * 4]);
            float av[8] = {a0.x, a0.y, a0.z, a0.w, a1.x, a1.y, a1.z, a1.w};
            float bv[4] = {b.x, b.y, b.z, b.w};
#pragma unroll
            for (int i = 0; i < 8; ++i)
#pragma unroll
                for (int j = 0; j < 4; ++j)
                    acc[i][j] = fmaf(av[i], bv[j], acc[i][j]);
        }
        __syncthreads();
    }

    float bb[4];
#pragma unroll
    for (int j = 0; j < 4; ++j) bb[j] = bias[tx * 4 + j];
#pragma unroll
    for (int i = 0; i < 8; ++i) {
        int m = m0 + ty * 8 + i;
        float4 o;
        o.x = acc[i][0] + bb[0];
        o.y = acc[i][1] + bb[1];
        o.z = acc[i][2] + bb[2];
        o.w = acc[i][3] + bb[3];
        *reinterpret_cast<float4*>(&g_u[(size_t)m * HG + tx * 4]) = o;
    }
}

__global__ __launch_bounds__(256) void gate1_kernel(
    const float* __restrict__ g1w, const float* __restrict__ g1b,
    const float* __restrict__ g2w, const float* __restrict__ g2b,
    float* __restrict__ out_gate)
{
    __shared__ float us[256][33];
    __shared__ float w1s[32][33];
    __shared__ float b1s[32];
    __shared__ float w2s[3][32];
    __shared__ float b2s[3];

    const int tid = threadIdx.x;
    const int m0 = blockIdx.x * 256;

    for (int idx = tid; idx < 256 * 32; idx += 256) {
        int r = idx >> 5, c = idx & 31;
        us[r][c] = g_u[(size_t)(m0 + r) * HG + c];
    }
    for (int idx = tid; idx < 32 * 32; idx += 256)
        w1s[idx >> 5][idx & 31] = g1w[idx];
    if (tid < 32) b1s[tid] = g1b[tid];
    if (tid < 96) w2s[tid / 32][tid % 32] = g2w[tid];
    if (tid < 3) b2s[tid] = g2b[tid];
    __syncthreads();

    const int m = m0 + tid;

    float eu[32];
#pragma unroll
    for (int k = 0; k < 32; ++k) {
        float x = us[tid][k];
        eu[k] = (x > 0.f) ? x : expm1f(x);
    }
    float ev[32];
#pragma unroll
    for (int j = 0; j < 32; ++j) {
        float v = b1s[j];
#pragma unroll
        for (int k = 0; k < 32; ++k) v = fmaf(eu[k], w1s[j][k], v);
        ev[j] = (v > 0.f) ? v : expm1f(v);
    }
    float s[3];
#pragma unroll
    for (int e = 0; e < 3; ++e) {
        float v = b2s[e];
#pragma unroll
        for (int j = 0; j < 32; ++j) v = fmaf(ev[j], w2s[e][j], v);
        s[e] = v;
    }
    float mx = fmaxf(s[0], fmaxf(s[1], s[2]));
    float p0 = expf(s[0] - mx);
    float p1 = expf(s[1] - mx);
    float p2 = expf(s[2] - mx);
    float inv = 1.f / (p0 + p1 + p2);
    p0 *= inv; p1 *= inv; p2 *= inv;

    g_gate[(size_t)m * 3 + 0] = p0;
    g_gate[(size_t)m * 3 + 1] = p1;
    g_gate[(size_t)m * 3 + 2] = p2;
    out_gate[(size_t)m * 3 + 0] = p0;
    out_gate[(size_t)m * 3 + 1] = p1;
    out_gate[(size_t)m * 3 + 2] = p2;
}

// ---------------------------------------------------------------------------
// blend_mma v6: pure fp16 GEMM, persistent CTAs, cp.async 2-stage pipeline.
// Out[m,n] = act( sum_e gate[m,e] * ((A @ W_e^T)[m,n] + b_e[n]) )
// A and W single fp16 planes, fp32 accumulate.
// Block tile: M=128 x N=64 x E=3, 8 warps (warp tile 32x32 per expert).
//
// smem per stage (half units, row stride 72):
//   A 128*72 | W 192*72  = 23040 units (46080B)
// ---------------------------------------------------------------------------
#define ASTRIDE 72
#define AROWS 128
#define WROWS 192
#define STAGE_U ((AROWS + WROWS) * ASTRIDE)   // 23040 half units

template <int KDIM, int NOUT>
__device__ __forceinline__ void prefetch_chunk(
    __half* sm, int stage, int k0, int m0, int n0,
    const __half* __restrict__ A, const __half* __restrict__ W)
{
    const int tid = threadIdx.x;
    const uint32_t base = smem_u32(sm) + (uint32_t)stage * STAGE_U * 2;
    // A: 128 rows * 8 = 1024 chunks ; W: 192 rows * 8 = 1536 chunks
#pragma unroll
    for (int it = 0; it < 10; ++it) {
        int i = tid + it * 256;               // 0..2559
        uint32_t dst;
        const __half* src;
        if (i < 1024) {
            int row = i >> 3, c = i & 7;
            src = A + (size_t)(m0 + row) * KDIM + k0 + c * 8;
            dst = base + (uint32_t)(row * ASTRIDE + c * 8) * 2;
        } else {
            int j = i - 1024;                 // 0..1535
            int r = j >> 3, c = j & 7;        // r in [0,192)
            int e = r >> 6, n = r & 63;
            src = W + ((size_t)e * NOUT + n0 + n) * KDIM + k0 + c * 8;
            dst = base + (uint32_t)(AROWS * ASTRIDE + r * ASTRIDE + c * 8) * 2;
        }
        CP_ASYNC16(dst, src);
    }
}

template <int KDIM, int NOUT, bool RELU, bool FP32OUT>
__global__ __launch_bounds__(256, 1) void blend_mma(
    const __half* __restrict__ A, const __half* __restrict__ W,
    const float* __restrict__ bias,
    __half* __restrict__ Oh, float* __restrict__ Ofp)
{
    extern __shared__ __half smbuf[];

    constexpr int NTN = NOUT / 64;            // n-tiles
    constexpr int NT = (B_ROWS / 128) * NTN;  // total tiles
    constexpr int NCH = KDIM / 64;

    const int tid = threadIdx.x;
    const int w = tid >> 5, lane = tid & 31;
    const int wm = w & 3, wn = w >> 2;        // warps: 4 along M, 2 along N
    const int g = lane >> 2, t = lane & 3;
    const int stride = gridDim.x;

    int tile = blockIdx.x;
    if (tile >= NT) return;

    {
        int m0 = (tile / NTN) * 128, n0 = (tile % NTN) * 64;
        prefetch_chunk<KDIM, NOUT>(smbuf, 0, 0, m0, n0, A, W);
        CP_COMMIT();
    }
    int buf = 0;

    while (tile < NT) {
        const int m0 = (tile / NTN) * 128;
        const int n0 = (tile % NTN) * 64;

        float gv[2][2][3];
#pragma unroll
        for (int mt = 0; mt < 2; ++mt)
#pragma unroll
            for (int h = 0; h < 2; ++h) {
                int m = m0 + wm * 32 + mt * 16 + g + h * 8;
                gv[mt][h][0] = g_gate[(size_t)m * 3 + 0];
                gv[mt][h][1] = g_gate[(size_t)m * 3 + 1];
                gv[mt][h][2] = g_gate[(size_t)m * 3 + 2];
            }
        float bb[3][4][2];
#pragma unroll
        for (int e = 0; e < 3; ++e)
#pragma unroll
            for (int nt = 0; nt < 4; ++nt) {
                int n = n0 + wn * 32 + nt * 8 + t * 2;
                bb[e][nt][0] = bias[e * NOUT + n];
                bb[e][nt][1] = bias[e * NOUT + n + 1];
            }

        float acc[3][2][4][4];
#pragma unroll
        for (int e = 0; e < 3; ++e)
#pragma unroll
            for (int mt = 0; mt < 2; ++mt)
#pragma unroll
                for (int nt = 0; nt < 4; ++nt)
#pragma unroll
                    for (int c = 0; c < 4; ++c) acc[e][mt][nt][c] = 0.f;

        for (int ch = 0; ch < NCH; ++ch) {
            int ntile, nch;
            if (ch + 1 < NCH) { ntile = tile; nch = ch + 1; }
            else { ntile = tile + stride; nch = 0; }
            if (ntile < NT) {
                int nm0 = (ntile / NTN) * 128, nn0 = (ntile % NTN) * 64;
                prefetch_chunk<KDIM, NOUT>(smbuf, buf ^ 1, nch * 64, nm0, nn0, A, W);
                CP_COMMIT();
                CP_WAIT1();
            } else {
                CP_WAIT0();
            }
            __syncthreads();

            const __half* sA = smbuf + buf * STAGE_U;
            const __half* sW = sA + AROWS * ASTRIDE;

#pragma unroll
            for (int ks = 0; ks < 64; ks += 16) {
                unsigned a[2][4];
#pragma unroll
                for (int mt = 0; mt < 2; ++mt) {
                    int r0 = (wm * 32 + mt * 16 + g) * ASTRIDE + ks + t * 2;
                    int r1 = r0 + 8 * ASTRIDE;
                    a[mt][0] = lds32h(sA + r0);
                    a[mt][1] = lds32h(sA + r1);
                    a[mt][2] = lds32h(sA + r0 + 8);
                    a[mt][3] = lds32h(sA + r1 + 8);
                }
#pragma unroll
                for (int e = 0; e < 3; ++e) {
                    unsigned b[4][2];
#pragma unroll
                    for (int nt = 0; nt < 4; ++nt) {
                        int c0 = (e * 64 + wn * 32 + nt * 8 + g) * ASTRIDE + ks + t * 2;
                        b[nt][0] = lds32h(sW + c0);
                        b[nt][1] = lds32h(sW + c0 + 8);
                    }
#pragma unroll
                    for (int mt = 0; mt < 2; ++mt)
#pragma unroll
                        for (int nt = 0; nt < 4; ++nt)
                            mma16816h(acc[e][mt][nt], a[mt], b[nt]);
                }
            }
            buf ^= 1;
            __syncthreads();
        }

        // ---------------- epilogue (register-only operands) ----------------
#pragma unroll
        for (int mt = 0; mt < 2; ++mt)
#pragma unroll
            for (int h = 0; h < 2; ++h) {
                int m = m0 + wm * 32 + mt * 16 + g + h * 8;
                float ga = gv[mt][h][0], gb = gv[mt][h][1], gc = gv[mt][h][2];
#pragma unroll
                for (int nt = 0; nt < 4; ++nt) {
                    int n = n0 + wn * 32 + nt * 8 + t * 2;
                    float v0 = ga * (acc[0][mt][nt][h * 2 + 0] + bb[0][nt][0])
                             + gb * (acc[1][mt][nt][h * 2 + 0] + bb[1][nt][0])
                             + gc * (acc[2][mt][nt][h * 2 + 0] + bb[2][nt][0]);
                    float v1 = ga * (acc[0][mt][nt][h * 2 + 1] + bb[0][nt][1])
                             + gb * (acc[1][mt][nt][h * 2 + 1] + bb[1][nt][1])
                             + gc * (acc[2][mt][nt][h * 2 + 1] + bb[2][nt][1]);
                    if (RELU) { v0 = fmaxf(v0, 0.f); v1 = fmaxf(v1, 0.f); }
                    if (FP32OUT) {
                        float2 o = {v0, v1};
                        *reinterpret_cast<float2*>(&Ofp[(size_t)m * NOUT + n]) = o;
                    } else {
                        *reinterpret_cast<__half2*>(&Oh[(size_t)m * NOUT + n]) =
                            __half2{__float2half_rn(v0), __float2half_rn(v1)};
                    }
                }
            }

        tile += stride;
    }
}

// ---------------------------------------------------------------------------
// Launch
// ---------------------------------------------------------------------------
extern "C" void kernel_launch(void* const* d_in, const int* in_sizes, int n_in,
                              void* d_out, int out_size)
{
    const float* f1  = (const float*)d_in[0];
    const float* f2  = (const float*)d_in[1];
    const float* lat = (const float*)d_in[2];
    const float* g0w = (const float*)d_in[3];
    const float* g0b = (const float*)d_in[4];
    const float* g1w = (const float*)d_in[5];
    const float* g1b = (const float*)d_in[6];
    const float* g2w = (const float*)d_in[7];
    const float* g2b = (const float*)d_in[8];
    const float* W1  = (const float*)d_in[9];
    const float* b1  = (const float*)d_in[10];
    const float* W2  = (const float*)d_in[11];
    const float* b2  = (const float*)d_in[12];
    const float* W3  = (const float*)d_in[13];
    const float* b3  = (const float*)d_in[14];
    const float* W4  = (const float*)d_in[15];
    const float* b4  = (const float*)d_in[16];

    float* out      = (float*)d_out;
    float* gate_out = out + (size_t)B_ROWS * LATD;

    __half *w1, *w2, *w3, *w4, *x, *h1, *h2;
    cudaGetSymbolAddress((void**)&w1, g_w1);
    cudaGetSymbolAddress((void**)&w2, g_w2);
    cudaGetSymbolAddress((void**)&w3, g_w3);
    cudaGetSymbolAddress((void**)&w4, g_w4);
    cudaGetSymbolAddress((void**)&x,  g_x);
    cudaGetSymbolAddress((void**)&h1, g_h1);
    cudaGetSymbolAddress((void**)&h2, g_h2);

    int nsm = 148;
    cudaDeviceGetAttribute(&nsm, cudaDevAttrMultiProcessorCount, 0);

    // conversions
    {
        int n4 = NE * HID * NIN / 4;
        convert_h<<<(n4 + 255) / 256, 256>>>(W1, w1, n4);
        n4 = NE * HID * HID / 4;
        convert_h<<<(n4 + 255) / 256, 256>>>(W2, w2, n4);
        convert_h<<<(n4 + 255) / 256, 256>>>(W3, w3, n4);
        n4 = NE * LATD * HID / 4;
        convert_h<<<(n4 + 255) / 256, 256>>>(W4, w4, n4);
        int nx = B_ROWS * (NIN / 4);
        xprep_kernel<<<nx / 256, 256>>>(f1, f2, lat);
    }

    // gate path
    gate0_kernel<<<B_ROWS / 256, 256>>>(f1, f2, lat, g0w, g0b);
    gate1_kernel<<<B_ROWS / 256, 256>>>(g1w, g1b, g2w, g2b, gate_out);

    // blend layers — persistent grid, dynamic smem (2 stages of 46080B)
    constexpr int SMEM_BYTES = 2 * STAGE_U * 2;   // 92160

    cudaFuncSetAttribute(blend_mma<NIN, HID, true, false>,
                         cudaFuncAttributeMaxDynamicSharedMemorySize, SMEM_BYTES);
    cudaFuncSetAttribute(blend_mma<HID, HID, true, false>,
                         cudaFuncAttributeMaxDynamicSharedMemorySize, SMEM_BYTES);
    cudaFuncSetAttribute(blend_mma<HID, LATD, false, true>,
                         cudaFuncAttributeMaxDynamicSharedMemorySize, SMEM_BYTES);

    blend_mma<NIN, HID, true, false><<<nsm, 256, SMEM_BYTES>>>(
        x, w1, b1, h1, nullptr);
    blend_mma<HID, HID, true, false><<<nsm, 256, SMEM_BYTES>>>(
        h1, w2, b2, h2, nullptr);
    blend_mma<HID, HID, true, false><<<nsm, 256, SMEM_BYTES>>>(
        h2, w3, b3, h1, nullptr);
    blend_mma<HID, LATD, false, true><<<nsm, 256, SMEM_BYTES>>>(
        h1, w4, b4, nullptr, out);
}

// round 11
// speedup vs baseline: 2.5615x; 1.0507x over previous
#include <cuda_runtime.h>
#include <cuda_bf16.h>
#include <cuda_fp16.h>
#include <math.h>
#include <stdint.h>

// Problem constants
#define B_ROWS 131072
#define FEAT 256
#define LATD 128
#define NIN 640           // 2*FEAT + LATD
#define HG 32
#define HID 512
#define NE 3

// ---------------------------------------------------------------------------
// Scratch (device globals — no runtime allocation allowed)
// ---------------------------------------------------------------------------
__device__ float g_u[(size_t)B_ROWS * HG];
__device__ float g_gate[(size_t)B_ROWS * NE];

// single-plane fp16 activations
__device__ __half g_x[(size_t)B_ROWS * NIN];
__device__ __half g_h1[(size_t)B_ROWS * HID];
__device__ __half g_h2[(size_t)B_ROWS * HID];

// single-plane fp16 weights
__device__ __half g_w1[NE * HID * NIN];
__device__ __half g_w2[NE * HID * HID];
__device__ __half g_w3[NE * HID * HID];
__device__ __half g_w4[NE * LATD * HID];

// ---------------------------------------------------------------------------
// helpers
// ---------------------------------------------------------------------------
__device__ __forceinline__ uint32_t smem_u32(const void* p) {
    uint32_t a;
    asm("{ .reg .u64 t; cvta.to.shared.u64 t, %1; cvt.u32.u64 %0, t; }" : "=r"(a) : "l"(p));
    return a;
}

#define CP_ASYNC16(dst, src) \
    asm volatile("cp.async.cg.shared.global [%0], [%1], 16;" :: "r"(dst), "l"(src))
#define CP_COMMIT() asm volatile("cp.async.commit_group;" ::: "memory")
#define CP_WAIT2()  asm volatile("cp.async.wait_group 2;" ::: "memory")

__device__ __forceinline__ void mma16816h(float* c, const unsigned* a, const unsigned* b) {
    asm volatile(
        "mma.sync.aligned.m16n8k16.row.col.f32.f16.f16.f32 "
        "{%0,%1,%2,%3}, {%4,%5,%6,%7}, {%8,%9}, {%0,%1,%2,%3};\n"
        : "+f"(c[0]), "+f"(c[1]), "+f"(c[2]), "+f"(c[3])
        : "r"(a[0]), "r"(a[1]), "r"(a[2]), "r"(a[3]), "r"(b[0]), "r"(b[1]));
}

__device__ __forceinline__ unsigned lds32h(const __half* p) {
    return *reinterpret_cast<const unsigned*>(p);
}

// ---------------------------------------------------------------------------
// prep kernels
// ---------------------------------------------------------------------------
__global__ __launch_bounds__(256) void convert_h(
    const float* __restrict__ src, __half* __restrict__ dst, int n4)
{
    int i = blockIdx.x * blockDim.x + threadIdx.x;
    if (i >= n4) return;
    float4 v = reinterpret_cast<const float4*>(src)[i];
    __half2* dp = reinterpret_cast<__half2*>(dst) + i * 2;
    dp[0] = __half2{__float2half_rn(v.x), __float2half_rn(v.y)};
    dp[1] = __half2{__float2half_rn(v.z), __float2half_rn(v.w)};
}

__global__ __launch_bounds__(256) void xprep_kernel(
    const float* __restrict__ f1, const float* __restrict__ f2,
    const float* __restrict__ lat)
{
    int i = blockIdx.x * blockDim.x + threadIdx.x;
    int row = i / (NIN / 4);
    int kk = (i % (NIN / 4)) * 4;
    float4 v;
    if (kk < FEAT)
        v = *reinterpret_cast<const float4*>(&f1[(size_t)row * FEAT + kk]);
    else if (kk < 2 * FEAT)
        v = *reinterpret_cast<const float4*>(&f2[(size_t)row * FEAT + kk - FEAT]);
    else
        v = *reinterpret_cast<const float4*>(&lat[(size_t)row * LATD + kk - 2 * FEAT]);
    size_t base = (size_t)row * NIN + kk;
    *reinterpret_cast<__half2*>(&g_x[base]) =
        __half2{__float2half_rn(v.x), __float2half_rn(v.y)};
    *reinterpret_cast<__half2*>(&g_x[base + 2]) =
        __half2{__float2half_rn(v.z), __float2half_rn(v.w)};
}

// gate0 reading fp16 g_x (4x less traffic than fp32 inputs)
__global__ __launch_bounds__(256) void gate0_kernel(
    const float* __restrict__ w, const float* __restrict__ bias)
{
    __shared__ float As[16][260];
    __shared__ float Ws[16][36];

    const int tid = threadIdx.x;
    const int tx = tid & 7;
    const int ty = tid >> 3;
    const int m0 = blockIdx.x * 256;

    float acc[8][4];
#pragma unroll
    for (int i = 0; i < 8; ++i)
#pragma unroll
        for (int j = 0; j < 4; ++j) acc[i][j] = 0.f;

    for (int k0 = 0; k0 < NIN; k0 += 16) {
        // A tile: 256 rows x 16 halves = 512 chunks of 8 halves, 2 per thread
#pragma unroll
        for (int r = 0; r < 2; ++r) {
            int idx = r * 256 + tid;
            int row = idx >> 1;
            int c = (idx & 1) * 8;
            uint4 vv = *reinterpret_cast<const uint4*>(
                &g_x[(size_t)(m0 + row) * NIN + k0 + c]);
            const __half2* hp = reinterpret_cast<const __half2*>(&vv);
#pragma unroll
            for (int q = 0; q < 4; ++q) {
                float2 f = __half22float2(hp[q]);
                As[c + q * 2 + 0][row] = f.x;
                As[c + q * 2 + 1][row] = f.y;
            }
        }
        if (tid < 128) {
            int n = tid >> 2;
            int kq = (tid & 3) * 4;
            float4 v = *reinterpret_cast<const float4*>(&w[(size_t)n * NIN + k0 + kq]);
            Ws[kq + 0][n] = v.x; Ws[kq + 1][n] = v.y;
            Ws[kq + 2][n] = v.z; Ws[kq + 3][n] = v.w;
        }
        __syncthreads();
#pragma unroll
        for (int k = 0; k < 16; ++k) {
            const float4 a0 = *reinterpret_cast<const float4*>(&As[k][ty * 8]);
            const float4 a1 = *reinterpret_cast<const float4*>(&As[k][ty * 8 + 4]);
            const float4 b  = *reinterpret_cast<const float4*>(&Ws[k][tx * 4]);
            float av[8] = {a0.x, a0.y, a0.z, a0.w, a1.x, a1.y, a1.z, a1.w};
            float bv[4] = {b.x, b.y, b.z, b.w};
#pragma unroll
            for (int i = 0; i < 8; ++i)
#pragma unroll
                for (int j = 0; j < 4; ++j)
                    acc[i][j] = fmaf(av[i], bv[j], acc[i][j]);
        }
        __syncthreads();
    }

    float bb[4];
#pragma unroll
    for (int j = 0; j < 4; ++j) bb[j] = bias[tx * 4 + j];
#pragma unroll
    for (int i = 0; i < 8; ++i) {
        int m = m0 + ty * 8 + i;
        float4 o;
        o.x = acc[i][0] + bb[0];
        o.y = acc[i][1] + bb[1];
        o.z = acc[i][2] + bb[2];
        o.w = acc[i][3] + bb[3];
        *reinterpret_cast<float4*>(&g_u[(size_t)m * HG + tx * 4]) = o;
    }
}

__global__ __launch_bounds__(256) void gate1_kernel(
    const float* __restrict__ g1w, const float* __restrict__ g1b,
    const float* __restrict__ g2w, const float* __restrict__ g2b,
    float* __restrict__ out_gate)
{
    __shared__ float us[256][33];
    __shared__ float w1s[32][33];
    __shared__ float b1s[32];
    __shared__ float w2s[3][32];
    __shared__ float b2s[3];

    const int tid = threadIdx.x;
    const int m0 = blockIdx.x * 256;

    for (int idx = tid; idx < 256 * 32; idx += 256) {
        int r = idx >> 5, c = idx & 31;
        us[r][c] = g_u[(size_t)(m0 + r) * HG + c];
    }
    for (int idx = tid; idx < 32 * 32; idx += 256)
        w1s[idx >> 5][idx & 31] = g1w[idx];
    if (tid < 32) b1s[tid] = g1b[tid];
    if (tid < 96) w2s[tid / 32][tid % 32] = g2w[tid];
    if (tid < 3) b2s[tid] = g2b[tid];
    __syncthreads();

    const int m = m0 + tid;

    float eu[32];
#pragma unroll
    for (int k = 0; k < 32; ++k) {
        float x = us[tid][k];
        eu[k] = (x > 0.f) ? x : expm1f(x);
    }
    float ev[32];
#pragma unroll
    for (int j = 0; j < 32; ++j) {
        float v = b1s[j];
#pragma unroll
        for (int k = 0; k < 32; ++k) v = fmaf(eu[k], w1s[j][k], v);
        ev[j] = (v > 0.f) ? v : expm1f(v);
    }
    float s[3];
#pragma unroll
    for (int e = 0; e < 3; ++e) {
        float v = b2s[e];
#pragma unroll
        for (int j = 0; j < 32; ++j) v = fmaf(ev[j], w2s[e][j], v);
        s[e] = v;
    }
    float mx = fmaxf(s[0], fmaxf(s[1], s[2]));
    float p0 = expf(s[0] - mx);
    float p1 = expf(s[1] - mx);
    float p2 = expf(s[2] - mx);
    float inv = 1.f / (p0 + p1 + p2);
    p0 *= inv; p1 *= inv; p2 *= inv;

    g_gate[(size_t)m * 3 + 0] = p0;
    g_gate[(size_t)m * 3 + 1] = p1;
    g_gate[(size_t)m * 3 + 2] = p2;
    out_gate[(size_t)m * 3 + 0] = p0;
    out_gate[(size_t)m * 3 + 1] = p1;
    out_gate[(size_t)m * 3 + 2] = p2;
}

// ---------------------------------------------------------------------------
// blend_mma v7: pure fp16 GEMM, persistent CTAs, 4-stage cp.async pipeline,
// ONE barrier per K-chunk.
// Out[m,n] = act( sum_e gate[m,e] * ((A @ W_e^T)[m,n] + b_e[n]) )
// Block tile: M=128 x N=64 x E=3, 8 warps (warp tile 32x32 per expert).
//
// smem per stage (half units, row stride 72):
//   A 128*72 | W 192*72  = 23040 units (46080B), 4 stages = 184320B
// ---------------------------------------------------------------------------
#define ASTRIDE 72
#define AROWS 128
#define WROWS 192
#define STAGE_U ((AROWS + WROWS) * ASTRIDE)   // 23040 half units

template <int KDIM, int NOUT>
__device__ __forceinline__ void prefetch_chunk(
    __half* sm, int stage, int k0, int m0, int n0,
    const __half* __restrict__ A, const __half* __restrict__ W)
{
    const int tid = threadIdx.x;
    const uint32_t base = smem_u32(sm) + (uint32_t)stage * STAGE_U * 2;
    // A: 128 rows * 8 = 1024 chunks ; W: 192 rows * 8 = 1536 chunks
#pragma unroll
    for (int it = 0; it < 10; ++it) {
        int i = tid + it * 256;               // 0..2559
        uint32_t dst;
        const __half* src;
        if (i < 1024) {
            int row = i >> 3, c = i & 7;
            src = A + (size_t)(m0 + row) * KDIM + k0 + c * 8;
            dst = base + (uint32_t)(row * ASTRIDE + c * 8) * 2;
        } else {
            int j = i - 1024;                 // 0..1535
            int r = j >> 3, c = j & 7;        // r in [0,192)
            int e = r >> 6, n = r & 63;
            src = W + ((size_t)e * NOUT + n0 + n) * KDIM + k0 + c * 8;
            dst = base + (uint32_t)(AROWS * ASTRIDE + r * ASTRIDE + c * 8) * 2;
        }
        CP_ASYNC16(dst, src);
    }
}

template <int KDIM, int NOUT, bool RELU, bool FP32OUT>
__global__ __launch_bounds__(256, 1) void blend_mma(
    const __half* __restrict__ A, const __half* __restrict__ W,
    const float* __restrict__ bias,
    __half* __restrict__ Oh, float* __restrict__ Ofp)
{
    extern __shared__ __half smbuf[];

    constexpr int NTN = NOUT / 64;            // n-tiles
    constexpr int NT = (B_ROWS / 128) * NTN;  // total tiles
    constexpr int NCH = KDIM / 64;            // K-chunks per tile (>=8)

    const int tid = threadIdx.x;
    const int w = tid >> 5, lane = tid & 31;
    const int wm = w & 3, wn = w >> 2;        // warps: 4 along M, 2 along N
    const int g = lane >> 2, t = lane & 3;
    const int stride = gridDim.x;

    int tile = blockIdx.x;
    if (tile >= NT) return;

    // prologue: prefetch chunks 0,1,2 of first tile into buffers 0,1,2
    {
        int m0 = (tile / NTN) * 128, n0 = (tile % NTN) * 64;
        prefetch_chunk<KDIM, NOUT>(smbuf, 0, 0, m0, n0, A, W);
        CP_COMMIT();
        prefetch_chunk<KDIM, NOUT>(smbuf, 1, 64, m0, n0, A, W);
        CP_COMMIT();
        prefetch_chunk<KDIM, NOUT>(smbuf, 2, 128, m0, n0, A, W);
        CP_COMMIT();
    }
    int gbuf = 0;   // buffer index of the chunk being consumed (global counter & 3)

    while (tile < NT) {
        const int m0 = (tile / NTN) * 128;
        const int n0 = (tile % NTN) * 64;

        float gv[2][2][3];
#pragma unroll
        for (int mt = 0; mt < 2; ++mt)
#pragma unroll
            for (int h = 0; h < 2; ++h) {
                int m = m0 + wm * 32 + mt * 16 + g + h * 8;
                gv[mt][h][0] = g_gate[(size_t)m * 3 + 0];
                gv[mt][h][1] = g_gate[(size_t)m * 3 + 1];
                gv[mt][h][2] = g_gate[(size_t)m * 3 + 2];
            }
        float bb[3][4][2];
#pragma unroll
        for (int e = 0; e < 3; ++e)
#pragma unroll
            for (int nt = 0; nt < 4; ++nt) {
                int n = n0 + wn * 32 + nt * 8 + t * 2;
                bb[e][nt][0] = bias[e * NOUT + n];
                bb[e][nt][1] = bias[e * NOUT + n + 1];
            }

        float acc[3][2][4][4];
#pragma unroll
        for (int e = 0; e < 3; ++e)
#pragma unroll
            for (int mt = 0; mt < 2; ++mt)
#pragma unroll
                for (int nt = 0; nt < 4; ++nt)
#pragma unroll
                    for (int c = 0; c < 4; ++c) acc[e][mt][nt][c] = 0.f;

        for (int ch = 0; ch < NCH; ++ch) {
            // chunk ch's data (buffer gbuf) is in group that wait_group 2 drains
            CP_WAIT2();
            __syncthreads();    // all data visible; all warps done with buffer gbuf+3 (reused now)

            // prefetch chunk ch+3 (possibly in next tile) into buffer (gbuf+3)&3
            {
                int pch = ch + 3, ptile = tile;
                if (pch >= NCH) { pch -= NCH; ptile += stride; }
                if (ptile < NT) {
                    int pm0 = (ptile / NTN) * 128, pn0 = (ptile % NTN) * 64;
                    prefetch_chunk<KDIM, NOUT>(smbuf, (gbuf + 3) & 3, pch * 64,
                                               pm0, pn0, A, W);
                }
                CP_COMMIT();   // always commit (possibly empty) to keep group count uniform
            }

            const __half* sA = smbuf + gbuf * STAGE_U;
            const __half* sW = sA + AROWS * ASTRIDE;

#pragma unroll
            for (int ks = 0; ks < 64; ks += 16) {
                unsigned a[2][4];
#pragma unroll
                for (int mt = 0; mt < 2; ++mt) {
                    int r0 = (wm * 32 + mt * 16 + g) * ASTRIDE + ks + t * 2;
                    int r1 = r0 + 8 * ASTRIDE;
                    a[mt][0] = lds32h(sA + r0);
                    a[mt][1] = lds32h(sA + r1);
                    a[mt][2] = lds32h(sA + r0 + 8);
                    a[mt][3] = lds32h(sA + r1 + 8);
                }
#pragma unroll
                for (int e = 0; e < 3; ++e) {
                    unsigned b[4][2];
#pragma unroll
                    for (int nt = 0; nt < 4; ++nt) {
                        int c0 = (e * 64 + wn * 32 + nt * 8 + g) * ASTRIDE + ks + t * 2;
                        b[nt][0] = lds32h(sW + c0);
                        b[nt][1] = lds32h(sW + c0 + 8);
                    }
#pragma unroll
                    for (int mt = 0; mt < 2; ++mt)
#pragma unroll
                        for (int nt = 0; nt < 4; ++nt)
                            mma16816h(acc[e][mt][nt], a[mt], b[nt]);
                }
            }
            gbuf = (gbuf + 1) & 3;
        }

        // ---------------- epilogue (register-only operands) ----------------
#pragma unroll
        for (int mt = 0; mt < 2; ++mt)
#pragma unroll
            for (int h = 0; h < 2; ++h) {
                int m = m0 + wm * 32 + mt * 16 + g + h * 8;
                float ga = gv[mt][h][0], gb = gv[mt][h][1], gc = gv[mt][h][2];
#pragma unroll
                for (int nt = 0; nt < 4; ++nt) {
                    int n = n0 + wn * 32 + nt * 8 + t * 2;
                    float v0 = ga * (acc[0][mt][nt][h * 2 + 0] + bb[0][nt][0])
                             + gb * (acc[1][mt][nt][h * 2 + 0] + bb[1][nt][0])
                             + gc * (acc[2][mt][nt][h * 2 + 0] + bb[2][nt][0]);
                    float v1 = ga * (acc[0][mt][nt][h * 2 + 1] + bb[0][nt][1])
                             + gb * (acc[1][mt][nt][h * 2 + 1] + bb[1][nt][1])
                             + gc * (acc[2][mt][nt][h * 2 + 1] + bb[2][nt][1]);
                    if (RELU) { v0 = fmaxf(v0, 0.f); v1 = fmaxf(v1, 0.f); }
                    if (FP32OUT) {
                        float2 o = {v0, v1};
                        *reinterpret_cast<float2*>(&Ofp[(size_t)m * NOUT + n]) = o;
                    } else {
                        *reinterpret_cast<__half2*>(&Oh[(size_t)m * NOUT + n]) =
                            __half2{__float2half_rn(v0), __float2half_rn(v1)};
                    }
                }
            }

        tile += stride;
    }
}

// ---------------------------------------------------------------------------
// Launch
// ---------------------------------------------------------------------------
extern "C" void kernel_launch(void* const* d_in, const int* in_sizes, int n_in,
                              void* d_out, int out_size)
{
    const float* f1  = (const float*)d_in[0];
    const float* f2  = (const float*)d_in[1];
    const float* lat = (const float*)d_in[2];
    const float* g0w = (const float*)d_in[3];
    const float* g0b = (const float*)d_in[4];
    const float* g1w = (const float*)d_in[5];
    const float* g1b = (const float*)d_in[6];
    const float* g2w = (const float*)d_in[7];
    const float* g2b = (const float*)d_in[8];
    const float* W1  = (const float*)d_in[9];
    const float* b1  = (const float*)d_in[10];
    const float* W2  = (const float*)d_in[11];
    const float* b2  = (const float*)d_in[12];
    const float* W3  = (const float*)d_in[13];
    const float* b3  = (const float*)d_in[14];
    const float* W4  = (const float*)d_in[15];
    const float* b4  = (const float*)d_in[16];

    float* out      = (float*)d_out;
    float* gate_out = out + (size_t)B_ROWS * LATD;

    __half *w1, *w2, *w3, *w4, *x, *h1, *h2;
    cudaGetSymbolAddress((void**)&w1, g_w1);
    cudaGetSymbolAddress((void**)&w2, g_w2);
    cudaGetSymbolAddress((void**)&w3, g_w3);
    cudaGetSymbolAddress((void**)&w4, g_w4);
    cudaGetSymbolAddress((void**)&x,  g_x);
    cudaGetSymbolAddress((void**)&h1, g_h1);
    cudaGetSymbolAddress((void**)&h2, g_h2);

    int nsm = 148;
    cudaDeviceGetAttribute(&nsm, cudaDevAttrMultiProcessorCount, 0);

    // conversions
    {
        int n4 = NE * HID * NIN / 4;
        convert_h<<<(n4 + 255) / 256, 256>>>(W1, w1, n4);
        n4 = NE * HID * HID / 4;
        convert_h<<<(n4 + 255) / 256, 256>>>(W2, w2, n4);
        convert_h<<<(n4 + 255) / 256, 256>>>(W3, w3, n4);
        n4 = NE * LATD * HID / 4;
        convert_h<<<(n4 + 255) / 256, 256>>>(W4, w4, n4);
        int nx = B_ROWS * (NIN / 4);
        xprep_kernel<<<nx / 256, 256>>>(f1, f2, lat);
    }

    // gate path (gate0 reads fp16 g_x -> must follow xprep; stream order OK)
    gate0_kernel<<<B_ROWS / 256, 256>>>(g0w, g0b);
    gate1_kernel<<<B_ROWS / 256, 256>>>(g1w, g1b, g2w, g2b, gate_out);

    // blend layers — persistent grid, dynamic smem (4 stages of 46080B)
    constexpr int SMEM_BYTES = 4 * STAGE_U * 2;   // 184320

    cudaFuncSetAttribute(blend_mma<NIN, HID, true, false>,
                         cudaFuncAttributeMaxDynamicSharedMemorySize, SMEM_BYTES);
    cudaFuncSetAttribute(blend_mma<HID, HID, true, false>,
                         cudaFuncAttributeMaxDynamicSharedMemorySize, SMEM_BYTES);
    cudaFuncSetAttribute(blend_mma<HID, LATD, false, true>,
                         cudaFuncAttributeMaxDynamicSharedMemorySize, SMEM_BYTES);

    blend_mma<NIN, HID, true, false><<<nsm, 256, SMEM_BYTES>>>(
        x, w1, b1, h1, nullptr);
    blend_mma<HID, HID, true, false><<<nsm, 256, SMEM_BYTES>>>(
        h1, w2, b2, h2, nullptr);
    blend_mma<HID, HID, true, false><<<nsm, 256, SMEM_BYTES>>>(
        h2, w3, b3, h1, nullptr);
    blend_mma<HID, LATD, false, true><<<nsm, 256, SMEM_BYTES>>>(
        h1, w4, b4, nullptr, out);
}

// round 12
// speedup vs baseline: 2.5847x; 1.0091x over previous
#include <cuda_runtime.h>
#include <cuda_bf16.h>
#include <cuda_fp16.h>
#include <math.h>
#include <stdint.h>

// Problem constants
#define B_ROWS 131072
#define FEAT 256
#define LATD 128
#define NIN 640           // 2*FEAT + LATD
#define HG 32
#define HID 512
#define NE 3

// ---------------------------------------------------------------------------
// Scratch (device globals — no runtime allocation allowed)
// ---------------------------------------------------------------------------
__device__ float g_gate[(size_t)B_ROWS * NE];

// single-plane fp16 activations
__device__ __half g_x[(size_t)B_ROWS * NIN];
__device__ __half g_h1[(size_t)B_ROWS * HID];
__device__ __half g_h2[(size_t)B_ROWS * HID];

// single-plane fp16 weights
__device__ __half g_w1[NE * HID * NIN];
__device__ __half g_w2[NE * HID * HID];
__device__ __half g_w3[NE * HID * HID];
__device__ __half g_w4[NE * LATD * HID];

// ---------------------------------------------------------------------------
// helpers
// ---------------------------------------------------------------------------
__device__ __forceinline__ uint32_t smem_u32(const void* p) {
    uint32_t a;
    asm("{ .reg .u64 t; cvta.to.shared.u64 t, %1; cvt.u32.u64 %0, t; }" : "=r"(a) : "l"(p));
    return a;
}

#define CP_ASYNC16(dst, src) \
    asm volatile("cp.async.cg.shared.global [%0], [%1], 16;" :: "r"(dst), "l"(src))
#define CP_COMMIT() asm volatile("cp.async.commit_group;" ::: "memory")
#define CP_WAIT0()  asm volatile("cp.async.wait_group 0;" ::: "memory")

__device__ __forceinline__ void mma16816h(float* c, const unsigned* a, const unsigned* b) {
    asm volatile(
        "mma.sync.aligned.m16n8k16.row.col.f32.f16.f16.f32 "
        "{%0,%1,%2,%3}, {%4,%5,%6,%7}, {%8,%9}, {%0,%1,%2,%3};\n"
        : "+f"(c[0]), "+f"(c[1]), "+f"(c[2]), "+f"(c[3])
        : "r"(a[0]), "r"(a[1]), "r"(a[2]), "r"(a[3]), "r"(b[0]), "r"(b[1]));
}

__device__ __forceinline__ unsigned lds32h(const __half* p) {
    return *reinterpret_cast<const unsigned*>(p);
}

// ---------------------------------------------------------------------------
// weight conversion
// ---------------------------------------------------------------------------
__global__ __launch_bounds__(256) void convert_h(
    const float* __restrict__ src, __half* __restrict__ dst, int n4)
{
    int i = blockIdx.x * blockDim.x + threadIdx.x;
    if (i >= n4) return;
    float4 v = reinterpret_cast<const float4*>(src)[i];
    __half2* dp = reinterpret_cast<__half2*>(dst) + i * 2;
    dp[0] = __half2{__float2half_rn(v.x), __float2half_rn(v.y)};
    dp[1] = __half2{__float2half_rn(v.z), __float2half_rn(v.w)};
}

// ---------------------------------------------------------------------------
// fused prep: reads fp32 inputs ONCE; writes g_x (fp16) AND computes the full
// gate path (x @ g0 -> elu -> g1 -> elu -> g2 -> softmax) -> g_gate + out_gate
// 256 rows per CTA, 256 threads.
// ---------------------------------------------------------------------------
__global__ __launch_bounds__(256) void prep_gate_kernel(
    const float* __restrict__ f1, const float* __restrict__ f2,
    const float* __restrict__ lat,
    const float* __restrict__ g0w, const float* __restrict__ g0b,
    const float* __restrict__ g1w, const float* __restrict__ g1b,
    const float* __restrict__ g2w, const float* __restrict__ g2b,
    float* __restrict__ out_gate)
{
    __shared__ float As[16][260];
    __shared__ float Ws[16][36];
    __shared__ float us[256][33];
    __shared__ float w1s[32][33];
    __shared__ float b1s[32];
    __shared__ float w2s[3][32];
    __shared__ float b2s[3];

    const int tid = threadIdx.x;
    const int tx = tid & 7;
    const int ty = tid >> 3;
    const int m0 = blockIdx.x * 256;

    // stage gate1/gate2 weights while the GEMM runs
    for (int idx = tid; idx < 32 * 32; idx += 256)
        w1s[idx >> 5][idx & 31] = g1w[idx];
    if (tid < 32) b1s[tid] = g1b[tid];
    if (tid < 96) w2s[tid / 32][tid % 32] = g2w[tid];
    if (tid < 3) b2s[tid] = g2b[tid];

    float acc[8][4];
#pragma unroll
    for (int i = 0; i < 8; ++i)
#pragma unroll
        for (int j = 0; j < 4; ++j) acc[i][j] = 0.f;

    for (int k0 = 0; k0 < NIN; k0 += 16) {
#pragma unroll
        for (int r = 0; r < 4; ++r) {
            int idx = r * 256 + tid;
            int m = idx >> 2;
            int kq = (idx & 3) * 4;
            int kg = k0 + kq;
            float4 v;
            if (kg < FEAT)
                v = *reinterpret_cast<const float4*>(&f1[(size_t)(m0 + m) * FEAT + kg]);
            else if (kg < 2 * FEAT)
                v = *reinterpret_cast<const float4*>(&f2[(size_t)(m0 + m) * FEAT + (kg - FEAT)]);
            else
                v = *reinterpret_cast<const float4*>(&lat[(size_t)(m0 + m) * LATD + (kg - 2 * FEAT)]);
            As[kq + 0][m] = v.x; As[kq + 1][m] = v.y;
            As[kq + 2][m] = v.z; As[kq + 3][m] = v.w;
            // emit fp16 x plane (single source-of-truth conversion)
            __half2 h01 = __half2{__float2half_rn(v.x), __float2half_rn(v.y)};
            __half2 h23 = __half2{__float2half_rn(v.z), __float2half_rn(v.w)};
            size_t xb = (size_t)(m0 + m) * NIN + kg;
            *reinterpret_cast<__half2*>(&g_x[xb])     = h01;
            *reinterpret_cast<__half2*>(&g_x[xb + 2]) = h23;
        }
        if (tid < 128) {
            int n = tid >> 2;
            int kq = (tid & 3) * 4;
            float4 v = *reinterpret_cast<const float4*>(&g0w[(size_t)n * NIN + k0 + kq]);
            Ws[kq + 0][n] = v.x; Ws[kq + 1][n] = v.y;
            Ws[kq + 2][n] = v.z; Ws[kq + 3][n] = v.w;
        }
        __syncthreads();
#pragma unroll
        for (int k = 0; k < 16; ++k) {
            const float4 a0 = *reinterpret_cast<const float4*>(&As[k][ty * 8]);
            const float4 a1 = *reinterpret_cast<const float4*>(&As[k][ty * 8 + 4]);
            const float4 b  = *reinterpret_cast<const float4*>(&Ws[k][tx * 4]);
            float av[8] = {a0.x, a0.y, a0.z, a0.w, a1.x, a1.y, a1.z, a1.w};
            float bv[4] = {b.x, b.y, b.z, b.w};
#pragma unroll
            for (int i = 0; i < 8; ++i)
#pragma unroll
                for (int j = 0; j < 4; ++j)
                    acc[i][j] = fmaf(av[i], bv[j], acc[i][j]);
        }
        __syncthreads();
    }

    // u -> smem (add bias)
    float bb[4];
#pragma unroll
    for (int j = 0; j < 4; ++j) bb[j] = g0b[tx * 4 + j];
#pragma unroll
    for (int i = 0; i < 8; ++i)
#pragma unroll
        for (int j = 0; j < 4; ++j)
            us[ty * 8 + i][tx * 4 + j] = acc[i][j] + bb[j];
    __syncthreads();

    // gate tail: one thread per row
    const int m = m0 + tid;

    float eu[32];
#pragma unroll
    for (int k = 0; k < 32; ++k) {
        float x = us[tid][k];
        eu[k] = (x > 0.f) ? x : expm1f(x);
    }
    float ev[32];
#pragma unroll
    for (int j = 0; j < 32; ++j) {
        float v = b1s[j];
#pragma unroll
        for (int k = 0; k < 32; ++k) v = fmaf(eu[k], w1s[j][k], v);
        ev[j] = (v > 0.f) ? v : expm1f(v);
    }
    float s[3];
#pragma unroll
    for (int e = 0; e < 3; ++e) {
        float v = b2s[e];
#pragma unroll
        for (int j = 0; j < 32; ++j) v = fmaf(ev[j], w2s[e][j], v);
        s[e] = v;
    }
    float mx = fmaxf(s[0], fmaxf(s[1], s[2]));
    float p0 = expf(s[0] - mx);
    float p1 = expf(s[1] - mx);
    float p2 = expf(s[2] - mx);
    float inv = 1.f / (p0 + p1 + p2);
    p0 *= inv; p1 *= inv; p2 *= inv;

    g_gate[(size_t)m * 3 + 0] = p0;
    g_gate[(size_t)m * 3 + 1] = p1;
    g_gate[(size_t)m * 3 + 2] = p2;
    out_gate[(size_t)m * 3 + 0] = p0;
    out_gate[(size_t)m * 3 + 1] = p1;
    out_gate[(size_t)m * 3 + 2] = p2;
}

// ---------------------------------------------------------------------------
// blend_mma v8: pure fp16 GEMM, persistent CTAs, K-chunk 128, 2-stage
// pipeline, ONE barrier per chunk.
// Out[m,n] = act( sum_e gate[m,e] * ((A @ W_e^T)[m,n] + b_e[n]) )
// Block tile: M=128 x N=64 x E=3, 8 warps (warp tile 32x32 per expert).
//
// smem per stage (half units, row stride 136 = 128k + 8 pad):
//   A 128*136 | W 192*136  = 43520 units (87040B), 2 stages = 174080B
// ---------------------------------------------------------------------------
#define ASTRIDE 136
#define AROWS 128
#define WROWS 192
#define STAGE_U ((AROWS + WROWS) * ASTRIDE)   // 43520 half units

template <int KDIM, int NOUT>
__device__ __forceinline__ void prefetch_chunk(
    __half* sm, int stage, int k0, int m0, int n0,
    const __half* __restrict__ A, const __half* __restrict__ W)
{
    const int tid = threadIdx.x;
    const uint32_t base = smem_u32(sm) + (uint32_t)stage * STAGE_U * 2;
    // A: 128 rows * 16 = 2048 chunks ; W: 192 rows * 16 = 3072 chunks
#pragma unroll
    for (int it = 0; it < 20; ++it) {
        int i = tid + it * 256;               // 0..5119
        uint32_t dst;
        const __half* src;
        if (i < 2048) {
            int row = i >> 4, c = i & 15;
            src = A + (size_t)(m0 + row) * KDIM + k0 + c * 8;
            dst = base + (uint32_t)(row * ASTRIDE + c * 8) * 2;
        } else {
            int j = i - 2048;                 // 0..3071
            int r = j >> 4, c = j & 15;       // r in [0,192)
            int e = r >> 6, n = r & 63;
            src = W + ((size_t)e * NOUT + n0 + n) * KDIM + k0 + c * 8;
            dst = base + (uint32_t)(AROWS * ASTRIDE + r * ASTRIDE + c * 8) * 2;
        }
        CP_ASYNC16(dst, src);
    }
}

template <int KDIM, int NOUT, bool RELU, bool FP32OUT>
__global__ __launch_bounds__(256, 1) void blend_mma(
    const __half* __restrict__ A, const __half* __restrict__ W,
    const float* __restrict__ bias,
    __half* __restrict__ Oh, float* __restrict__ Ofp)
{
    extern __shared__ __half smbuf[];

    constexpr int NTN = NOUT / 64;            // n-tiles
    constexpr int NT = (B_ROWS / 128) * NTN;  // total tiles
    constexpr int NCH = KDIM / 128;           // K-chunks per tile

    const int tid = threadIdx.x;
    const int w = tid >> 5, lane = tid & 31;
    const int wm = w & 3, wn = w >> 2;        // warps: 4 along M, 2 along N
    const int g = lane >> 2, t = lane & 3;
    const int stride = gridDim.x;

    int tile = blockIdx.x;
    if (tile >= NT) return;

    // prologue: prefetch chunk 0 of first tile into buffer 0
    {
        int m0 = (tile / NTN) * 128, n0 = (tile % NTN) * 64;
        prefetch_chunk<KDIM, NOUT>(smbuf, 0, 0, m0, n0, A, W);
        CP_COMMIT();
    }
    int gbuf = 0;

    while (tile < NT) {
        const int m0 = (tile / NTN) * 128;
        const int n0 = (tile % NTN) * 64;

        float gv[2][2][3];
#pragma unroll
        for (int mt = 0; mt < 2; ++mt)
#pragma unroll
            for (int h = 0; h < 2; ++h) {
                int m = m0 + wm * 32 + mt * 16 + g + h * 8;
                gv[mt][h][0] = g_gate[(size_t)m * 3 + 0];
                gv[mt][h][1] = g_gate[(size_t)m * 3 + 1];
                gv[mt][h][2] = g_gate[(size_t)m * 3 + 2];
            }
        float bb[3][4][2];
#pragma unroll
        for (int e = 0; e < 3; ++e)
#pragma unroll
            for (int nt = 0; nt < 4; ++nt) {
                int n = n0 + wn * 32 + nt * 8 + t * 2;
                bb[e][nt][0] = bias[e * NOUT + n];
                bb[e][nt][1] = bias[e * NOUT + n + 1];
            }

        float acc[3][2][4][4];
#pragma unroll
        for (int e = 0; e < 3; ++e)
#pragma unroll
            for (int mt = 0; mt < 2; ++mt)
#pragma unroll
                for (int nt = 0; nt < 4; ++nt)
#pragma unroll
                    for (int c = 0; c < 4; ++c) acc[e][mt][nt][c] = 0.f;

        for (int ch = 0; ch < NCH; ++ch) {
            // drain the group filling gbuf (committed last iteration/prologue)
            CP_WAIT0();
            __syncthreads();   // data visible to all warps; buf gbuf^1 free

            // prefetch next chunk (possibly next tile) into gbuf^1
            {
                int pch = ch + 1, ptile = tile;
                if (pch >= NCH) { pch = 0; ptile += stride; }
                if (ptile < NT) {
                    int pm0 = (ptile / NTN) * 128, pn0 = (ptile % NTN) * 64;
                    prefetch_chunk<KDIM, NOUT>(smbuf, gbuf ^ 1, pch * 128,
                                               pm0, pn0, A, W);
                    CP_COMMIT();
                }
            }

            const __half* sA = smbuf + gbuf * STAGE_U;
            const __half* sW = sA + AROWS * ASTRIDE;

#pragma unroll
            for (int ks = 0; ks < 128; ks += 16) {
                unsigned a[2][4];
#pragma unroll
                for (int mt = 0; mt < 2; ++mt) {
                    int r0 = (wm * 32 + mt * 16 + g) * ASTRIDE + ks + t * 2;
                    int r1 = r0 + 8 * ASTRIDE;
                    a[mt][0] = lds32h(sA + r0);
                    a[mt][1] = lds32h(sA + r1);
                    a[mt][2] = lds32h(sA + r0 + 8);
                    a[mt][3] = lds32h(sA + r1 + 8);
                }
#pragma unroll
                for (int e = 0; e < 3; ++e) {
                    unsigned b[4][2];
#pragma unroll
                    for (int nt = 0; nt < 4; ++nt) {
                        int c0 = (e * 64 + wn * 32 + nt * 8 + g) * ASTRIDE + ks + t * 2;
                        b[nt][0] = lds32h(sW + c0);
                        b[nt][1] = lds32h(sW + c0 + 8);
                    }
#pragma unroll
                    for (int mt = 0; mt < 2; ++mt)
#pragma unroll
                        for (int nt = 0; nt < 4; ++nt)
                            mma16816h(acc[e][mt][nt], a[mt], b[nt]);
                }
            }
            gbuf ^= 1;
        }

        // ---------------- epilogue (register-only operands) ----------------
#pragma unroll
        for (int mt = 0; mt < 2; ++mt)
#pragma unroll
            for (int h = 0; h < 2; ++h) {
                int m = m0 + wm * 32 + mt * 16 + g + h * 8;
                float ga = gv[mt][h][0], gb = gv[mt][h][1], gc = gv[mt][h][2];
#pragma unroll
                for (int nt = 0; nt < 4; ++nt) {
                    int n = n0 + wn * 32 + nt * 8 + t * 2;
                    float v0 = ga * (acc[0][mt][nt][h * 2 + 0] + bb[0][nt][0])
                             + gb * (acc[1][mt][nt][h * 2 + 0] + bb[1][nt][0])
                             + gc * (acc[2][mt][nt][h * 2 + 0] + bb[2][nt][0]);
                    float v1 = ga * (acc[0][mt][nt][h * 2 + 1] + bb[0][nt][1])
                             + gb * (acc[1][mt][nt][h * 2 + 1] + bb[1][nt][1])
                             + gc * (acc[2][mt][nt][h * 2 + 1] + bb[2][nt][1]);
                    if (RELU) { v0 = fmaxf(v0, 0.f); v1 = fmaxf(v1, 0.f); }
                    if (FP32OUT) {
                        float2 o = {v0, v1};
                        *reinterpret_cast<float2*>(&Ofp[(size_t)m * NOUT + n]) = o;
                    } else {
                        *reinterpret_cast<__half2*>(&Oh[(size_t)m * NOUT + n]) =
                            __half2{__float2half_rn(v0), __float2half_rn(v1)};
                    }
                }
            }

        tile += stride;
    }
}

// ---------------------------------------------------------------------------
// Launch
// ---------------------------------------------------------------------------
extern "C" void kernel_launch(void* const* d_in, const int* in_sizes, int n_in,
                              void* d_out, int out_size)
{
    const float* f1  = (const float*)d_in[0];
    const float* f2  = (const float*)d_in[1];
    const float* lat = (const float*)d_in[2];
    const float* g0w = (const float*)d_in[3];
    const float* g0b = (const float*)d_in[4];
    const float* g1w = (const float*)d_in[5];
    const float* g1b = (const float*)d_in[6];
    const float* g2w = (const float*)d_in[7];
    const float* g2b = (const float*)d_in[8];
    const float* W1  = (const float*)d_in[9];
    const float* b1  = (const float*)d_in[10];
    const float* W2  = (const float*)d_in[11];
    const float* b2  = (const float*)d_in[12];
    const float* W3  = (const float*)d_in[13];
    const float* b3  = (const float*)d_in[14];
    const float* W4  = (const float*)d_in[15];
    const float* b4  = (const float*)d_in[16];

    float* out      = (float*)d_out;
    float* gate_out = out + (size_t)B_ROWS * LATD;

    __half *w1, *w2, *w3, *w4, *x, *h1, *h2;
    cudaGetSymbolAddress((void**)&w1, g_w1);
    cudaGetSymbolAddress((void**)&w2, g_w2);
    cudaGetSymbolAddress((void**)&w3, g_w3);
    cudaGetSymbolAddress((void**)&w4, g_w4);
    cudaGetSymbolAddress((void**)&x,  g_x);
    cudaGetSymbolAddress((void**)&h1, g_h1);
    cudaGetSymbolAddress((void**)&h2, g_h2);

    int nsm = 148;
    cudaDeviceGetAttribute(&nsm, cudaDevAttrMultiProcessorCount, 0);

    // weight conversions
    {
        int n4 = NE * HID * NIN / 4;
        convert_h<<<(n4 + 255) / 256, 256>>>(W1, w1, n4);
        n4 = NE * HID * HID / 4;
        convert_h<<<(n4 + 255) / 256, 256>>>(W2, w2, n4);
        convert_h<<<(n4 + 255) / 256, 256>>>(W3, w3, n4);
        n4 = NE * LATD * HID / 4;
        convert_h<<<(n4 + 255) / 256, 256>>>(W4, w4, n4);
    }

    // fused prep: inputs -> g_x + full gate path
    prep_gate_kernel<<<B_ROWS / 256, 256>>>(f1, f2, lat, g0w, g0b,
                                            g1w, g1b, g2w, g2b, gate_out);

    // blend layers — persistent grid, dynamic smem (2 stages of 87040B)
    constexpr int SMEM_BYTES = 2 * STAGE_U * 2;   // 174080

    cudaFuncSetAttribute(blend_mma<NIN, HID, true, false>,
                         cudaFuncAttributeMaxDynamicSharedMemorySize, SMEM_BYTES);
    cudaFuncSetAttribute(blend_mma<HID, HID, true, false>,
                         cudaFuncAttributeMaxDynamicSharedMemorySize, SMEM_BYTES);
    cudaFuncSetAttribute(blend_mma<HID, LATD, false, true>,
                         cudaFuncAttributeMaxDynamicSharedMemorySize, SMEM_BYTES);

    blend_mma<NIN, HID, true, false><<<nsm, 256, SMEM_BYTES>>>(
        x, w1, b1, h1, nullptr);
    blend_mma<HID, HID, true, false><<<nsm, 256, SMEM_BYTES>>>(
        h1, w2, b2, h2, nullptr);
    blend_mma<HID, HID, true, false><<<nsm, 256, SMEM_BYTES>>>(
        h2, w3, b3, h1, nullptr);
    blend_mma<HID, LATD, false, true><<<nsm, 256, SMEM_BYTES>>>(
        h1, w4, b4, nullptr, out);
}